// round 4
// baseline (speedup 1.0000x reference)
#include <cuda_runtime.h>

#define BB   32
#define CC   512
#define HW2  1024
#define NW   77
#define WD   256
#define M_WE (BB * NW)   // 2464

// Scratch: we[b][n][k], k contiguous. 32*77*1024 floats = 10.1 MB.
__device__ float g_we[BB * NW * HW2];

// ---------------------------------------------------------------------------
// Kernel 1: we[m][k] = word_emb_flat[m][:] . W_fc[k][:] + b_fc[k]
// GEMM M=2464, N=1024, K=256 (both operands K-major -> A @ B^T).
// 64x64 tile, 256 threads, each thread 4x4.
// ---------------------------------------------------------------------------
__global__ void we_gemm(const float* __restrict__ we_in,
                        const float* __restrict__ Wfc,
                        const float* __restrict__ bfc) {
    __shared__ float As[64][33];
    __shared__ float Bs[64][33];

    const int tid = threadIdx.x;
    const int tx  = tid & 15;
    const int ty  = tid >> 4;
    const int m0  = blockIdx.y * 64;
    const int k0  = blockIdx.x * 64;

    float acc[4][4];
#pragma unroll
    for (int i = 0; i < 4; i++)
#pragma unroll
        for (int j = 0; j < 4; j++) acc[i][j] = 0.f;

    for (int d0 = 0; d0 < WD; d0 += 32) {
#pragma unroll
        for (int i = tid; i < 64 * 32; i += 256) {
            int r = i >> 5, c = i & 31;
            int m = m0 + r;
            As[r][c] = (m < M_WE) ? we_in[m * WD + d0 + c] : 0.f;
            Bs[r][c] = Wfc[(k0 + r) * WD + d0 + c];
        }
        __syncthreads();
#pragma unroll
        for (int dd = 0; dd < 32; dd++) {
            float a[4], b[4];
#pragma unroll
            for (int i = 0; i < 4; i++) a[i] = As[ty * 4 + i][dd];
#pragma unroll
            for (int j = 0; j < 4; j++) b[j] = Bs[tx * 4 + j][dd];
#pragma unroll
            for (int i = 0; i < 4; i++)
#pragma unroll
                for (int j = 0; j < 4; j++) acc[i][j] += a[i] * b[j];
        }
        __syncthreads();
    }

#pragma unroll
    for (int i = 0; i < 4; i++) {
        int m = m0 + ty * 4 + i;
        if (m < M_WE) {
#pragma unroll
            for (int j = 0; j < 4; j++) {
                int k = k0 + tx * 4 + j;
                g_we[m * HW2 + k] = acc[i][j] + bfc[k];
            }
        }
    }
}

// ---------------------------------------------------------------------------
// Kernel 2: fused  scores -> softmax -> att_feat  per (batch, 64-channel tile)
//   Phase 1: scores[c][n] = sum_k f[b,c,k] * we[b,n,k]   (GEMM 64x80xK=1024)
//   Phase 2: softmax over n (77 valid) in smem
//   Phase 3: out[c][k]   = sum_n att[c][n] * we[b,n,k]    (GEMM 64x1024xK=77)
// ---------------------------------------------------------------------------
__global__ void attn_fused(const float* __restrict__ feat,
                           float* __restrict__ out) {
    // Union buffer: phase1 tiles (As 64x33 + Bs 80x33 = 4752 f) vs
    //               phase3 tile  (Ws 77x64 = 4928 f)
    __shared__ float U[4928];
    __shared__ float S[64 * 81];   // scores / attention weights, padded stride 81

    float* As = U;              // [64][33]
    float* Bs = U + 64 * 33;    // [80][33]
    float* Ws = U;              // [77][64]

    const int tid = threadIdx.x;
    const int tx  = tid & 15;
    const int ty  = tid >> 4;
    const int b   = blockIdx.y;
    const int c0  = blockIdx.x * 64;

    const float* fb  = feat + ((size_t)b * CC + c0) * HW2;
    const float* web = g_we + (size_t)b * NW * HW2;
    float*       ob  = out  + ((size_t)b * CC + c0) * HW2;

    // ---- Phase 1: scores (64 channels x 80 n, n>=77 padded with zeros) ----
    float acc[4][5];
#pragma unroll
    for (int i = 0; i < 4; i++)
#pragma unroll
        for (int j = 0; j < 5; j++) acc[i][j] = 0.f;

    for (int k0 = 0; k0 < HW2; k0 += 32) {
#pragma unroll
        for (int i = tid; i < 64 * 32; i += 256) {
            int r = i >> 5, c = i & 31;
            As[r * 33 + c] = fb[r * HW2 + k0 + c];
        }
#pragma unroll
        for (int i = tid; i < 80 * 32; i += 256) {
            int r = i >> 5, c = i & 31;
            Bs[r * 33 + c] = (r < NW) ? web[r * HW2 + k0 + c] : 0.f;
        }
        __syncthreads();
#pragma unroll
        for (int kk = 0; kk < 32; kk++) {
            float a[4], bn[5];
#pragma unroll
            for (int i = 0; i < 4; i++) a[i] = As[(ty * 4 + i) * 33 + kk];
#pragma unroll
            for (int j = 0; j < 5; j++) bn[j] = Bs[(tx * 5 + j) * 33 + kk];
#pragma unroll
            for (int i = 0; i < 4; i++)
#pragma unroll
                for (int j = 0; j < 5; j++) acc[i][j] += a[i] * bn[j];
        }
        __syncthreads();
    }

    // store scores to smem
#pragma unroll
    for (int i = 0; i < 4; i++)
#pragma unroll
        for (int j = 0; j < 5; j++)
            S[(ty * 4 + i) * 81 + (tx * 5 + j)] = acc[i][j];
    __syncthreads();

    // ---- Phase 2: softmax over n (77) per channel row ----
    if (tid < 64) {
        float* row = S + tid * 81;
        float mx = -1e30f;
        for (int n = 0; n < NW; n++) mx = fmaxf(mx, row[n]);
        float s = 0.f;
        for (int n = 0; n < NW; n++) {
            float e = __expf(row[n] - mx);
            row[n] = e;
            s += e;
        }
        float inv = 1.f / s;
        for (int n = 0; n < NW; n++) row[n] *= inv;
    }
    __syncthreads();

    // ---- Phase 3: att_feat: out[c][k] = sum_n att[c][n] * we[n][k] ----
    for (int kc = 0; kc < HW2; kc += 64) {
        // load we tile [77][64]
        for (int i = tid; i < NW * 64; i += 256) {
            int r = i >> 6, c = i & 63;
            Ws[i] = web[r * HW2 + kc + c];
        }
        __syncthreads();

        float4 acc2[4];
#pragma unroll
        for (int i = 0; i < 4; i++) acc2[i] = make_float4(0.f, 0.f, 0.f, 0.f);

        for (int n = 0; n < NW; n++) {
            float4 wv = *(const float4*)&Ws[n * 64 + tx * 4];
#pragma unroll
            for (int i = 0; i < 4; i++) {
                float a = S[(ty * 4 + i) * 81 + n];
                acc2[i].x += a * wv.x;
                acc2[i].y += a * wv.y;
                acc2[i].z += a * wv.z;
                acc2[i].w += a * wv.w;
            }
        }

#pragma unroll
        for (int i = 0; i < 4; i++) {
            *(float4*)&ob[(ty * 4 + i) * HW2 + kc + tx * 4] = acc2[i];
        }
        __syncthreads();
    }
}

// ---------------------------------------------------------------------------
extern "C" void kernel_launch(void* const* d_in, const int* in_sizes, int n_in,
                              void* d_out, int out_size) {
    const float* feat     = (const float*)d_in[0];   // 32*512*32*32
    const float* word_emb = (const float*)d_in[1];   // 32*77*256
    const float* W_fc     = (const float*)d_in[2];   // 1024*256
    const float* b_fc     = (const float*)d_in[3];   // 1024
    float* out            = (float*)d_out;           // 32*512*1024

    (void)in_sizes; (void)n_in; (void)out_size;

    // Kernel 1: we = word_emb @ W_fc^T + b_fc
    dim3 g1(HW2 / 64, (M_WE + 63) / 64);   // (16, 39)
    we_gemm<<<g1, 256>>>(word_emb, W_fc, b_fc);

    // Kernel 2: fused scores/softmax/att_feat
    dim3 g2(CC / 64, BB);                  // (8, 32)
    attn_fused<<<g2, 256>>>(feat, out);
}

// round 5
// speedup vs baseline: 1.0061x; 1.0061x over previous
#include <cuda_runtime.h>

#define BB   32
#define CC   512
#define HW2  1024
#define NW   77
#define WD   256
#define M_WE (BB * NW)   // 2464

// Scratch: we[b][n][k], k contiguous. 32*77*1024 floats = 10.1 MB.
__device__ float g_we[BB * NW * HW2];

// ---------------------------------------------------------------------------
// Kernel 1: we[m][k] = word_emb_flat[m][:] . W_fc[k][:] + b_fc[k]
// GEMM M=2464, N=1024, K=256 (both operands K-major -> A @ B^T).
// 64x64 tile, 256 threads, each thread 4x4.
// ---------------------------------------------------------------------------
__global__ void we_gemm(const float* __restrict__ we_in,
                        const float* __restrict__ Wfc,
                        const float* __restrict__ bfc) {
    __shared__ float As[64][33];
    __shared__ float Bs[64][33];

    const int tid = threadIdx.x;
    const int tx  = tid & 15;
    const int ty  = tid >> 4;
    const int m0  = blockIdx.y * 64;
    const int k0  = blockIdx.x * 64;

    float acc[4][4];
#pragma unroll
    for (int i = 0; i < 4; i++)
#pragma unroll
        for (int j = 0; j < 4; j++) acc[i][j] = 0.f;

    for (int d0 = 0; d0 < WD; d0 += 32) {
#pragma unroll
        for (int i = tid; i < 64 * 32; i += 256) {
            int r = i >> 5, c = i & 31;
            int m = m0 + r;
            As[r][c] = (m < M_WE) ? we_in[m * WD + d0 + c] : 0.f;
            Bs[r][c] = Wfc[(k0 + r) * WD + d0 + c];
        }
        __syncthreads();
#pragma unroll
        for (int dd = 0; dd < 32; dd++) {
            float a[4], b[4];
#pragma unroll
            for (int i = 0; i < 4; i++) a[i] = As[ty * 4 + i][dd];
#pragma unroll
            for (int j = 0; j < 4; j++) b[j] = Bs[tx * 4 + j][dd];
#pragma unroll
            for (int i = 0; i < 4; i++)
#pragma unroll
                for (int j = 0; j < 4; j++) acc[i][j] += a[i] * b[j];
        }
        __syncthreads();
    }

#pragma unroll
    for (int i = 0; i < 4; i++) {
        int m = m0 + ty * 4 + i;
        if (m < M_WE) {
#pragma unroll
            for (int j = 0; j < 4; j++) {
                int k = k0 + tx * 4 + j;
                g_we[m * HW2 + k] = acc[i][j] + bfc[k];
            }
        }
    }
}

// ---------------------------------------------------------------------------
// Kernel 2: fused  scores -> softmax -> att_feat  per (batch, 64-channel tile)
//   Phase 1: scores[c][n] = sum_k f[b,c,k] * we[b,n,k]   (GEMM 64x80xK=1024)
//   Phase 2: softmax over n (77 valid) in smem
//   Phase 3: out[c][k]   = sum_n att[c][n] * we[b,n,k]    (GEMM 64x1024xK=77)
// ---------------------------------------------------------------------------
__global__ void attn_fused(const float* __restrict__ feat,
                           float* __restrict__ out) {
    // Union buffer: phase1 tiles (As 64x33 + Bs 80x33 = 4752 f) vs
    //               phase3 tile  (Ws 77x64 = 4928 f)
    __shared__ float U[4928];
    __shared__ float S[64 * 81];   // scores / attention weights, padded stride 81

    float* As = U;              // [64][33]
    float* Bs = U + 64 * 33;    // [80][33]
    float* Ws = U;              // [77][64]

    const int tid = threadIdx.x;
    const int tx  = tid & 15;
    const int ty  = tid >> 4;
    const int b   = blockIdx.y;
    const int c0  = blockIdx.x * 64;

    const float* fb  = feat + ((size_t)b * CC + c0) * HW2;
    const float* web = g_we + (size_t)b * NW * HW2;
    float*       ob  = out  + ((size_t)b * CC + c0) * HW2;

    // ---- Phase 1: scores (64 channels x 80 n, n>=77 padded with zeros) ----
    float acc[4][5];
#pragma unroll
    for (int i = 0; i < 4; i++)
#pragma unroll
        for (int j = 0; j < 5; j++) acc[i][j] = 0.f;

    for (int k0 = 0; k0 < HW2; k0 += 32) {
#pragma unroll
        for (int i = tid; i < 64 * 32; i += 256) {
            int r = i >> 5, c = i & 31;
            As[r * 33 + c] = fb[r * HW2 + k0 + c];
        }
#pragma unroll
        for (int i = tid; i < 80 * 32; i += 256) {
            int r = i >> 5, c = i & 31;
            Bs[r * 33 + c] = (r < NW) ? web[r * HW2 + k0 + c] : 0.f;
        }
        __syncthreads();
#pragma unroll
        for (int kk = 0; kk < 32; kk++) {
            float a[4], bn[5];
#pragma unroll
            for (int i = 0; i < 4; i++) a[i] = As[(ty * 4 + i) * 33 + kk];
#pragma unroll
            for (int j = 0; j < 5; j++) bn[j] = Bs[(tx * 5 + j) * 33 + kk];
#pragma unroll
            for (int i = 0; i < 4; i++)
#pragma unroll
                for (int j = 0; j < 5; j++) acc[i][j] += a[i] * bn[j];
        }
        __syncthreads();
    }

    // store scores to smem
#pragma unroll
    for (int i = 0; i < 4; i++)
#pragma unroll
        for (int j = 0; j < 5; j++)
            S[(ty * 4 + i) * 81 + (tx * 5 + j)] = acc[i][j];
    __syncthreads();

    // ---- Phase 2: softmax over n (77) per channel row ----
    if (tid < 64) {
        float* row = S + tid * 81;
        float mx = -1e30f;
        for (int n = 0; n < NW; n++) mx = fmaxf(mx, row[n]);
        float s = 0.f;
        for (int n = 0; n < NW; n++) {
            float e = __expf(row[n] - mx);
            row[n] = e;
            s += e;
        }
        float inv = 1.f / s;
        for (int n = 0; n < NW; n++) row[n] *= inv;
    }
    __syncthreads();

    // ---- Phase 3: att_feat: out[c][k] = sum_n att[c][n] * we[n][k] ----
    for (int kc = 0; kc < HW2; kc += 64) {
        // load we tile [77][64]
        for (int i = tid; i < NW * 64; i += 256) {
            int r = i >> 6, c = i & 63;
            Ws[i] = web[r * HW2 + kc + c];
        }
        __syncthreads();

        float4 acc2[4];
#pragma unroll
        for (int i = 0; i < 4; i++) acc2[i] = make_float4(0.f, 0.f, 0.f, 0.f);

        for (int n = 0; n < NW; n++) {
            float4 wv = *(const float4*)&Ws[n * 64 + tx * 4];
#pragma unroll
            for (int i = 0; i < 4; i++) {
                float a = S[(ty * 4 + i) * 81 + n];
                acc2[i].x += a * wv.x;
                acc2[i].y += a * wv.y;
                acc2[i].z += a * wv.z;
                acc2[i].w += a * wv.w;
            }
        }

#pragma unroll
        for (int i = 0; i < 4; i++) {
            *(float4*)&ob[(ty * 4 + i) * HW2 + kc + tx * 4] = acc2[i];
        }
        __syncthreads();
    }
}

// ---------------------------------------------------------------------------
extern "C" void kernel_launch(void* const* d_in, const int* in_sizes, int n_in,
                              void* d_out, int out_size) {
    const float* feat     = (const float*)d_in[0];   // 32*512*32*32
    const float* word_emb = (const float*)d_in[1];   // 32*77*256
    const float* W_fc     = (const float*)d_in[2];   // 1024*256
    const float* b_fc     = (const float*)d_in[3];   // 1024
    float* out            = (float*)d_out;           // 32*512*1024

    (void)in_sizes; (void)n_in; (void)out_size;

    // Kernel 1: we = word_emb @ W_fc^T + b_fc
    dim3 g1(HW2 / 64, (M_WE + 63) / 64);   // (16, 39)
    we_gemm<<<g1, 256>>>(word_emb, W_fc, b_fc);

    // Kernel 2: fused scores/softmax/att_feat
    dim3 g2(CC / 64, BB);                  // (8, 32)
    attn_fused<<<g2, 256>>>(feat, out);
}

// round 6
// speedup vs baseline: 1.0091x; 1.0029x over previous
#include <cuda_runtime.h>

#define BB   32
#define CC   512
#define HW2  1024
#define NW   77
#define WD   256
#define M_WE (BB * NW)   // 2464

// Scratch: we[b][n][k], k contiguous. 32*77*1024 floats = 10.1 MB.
__device__ float g_we[BB * NW * HW2];

// ---------------------------------------------------------------------------
// Kernel 1: we[m][k] = word_emb_flat[m][:] . W_fc[k][:] + b_fc[k]
// GEMM M=2464, N=1024, K=256 (both operands K-major -> A @ B^T).
// 64x64 tile, 256 threads, each thread 4x4.
// ---------------------------------------------------------------------------
__global__ void we_gemm(const float* __restrict__ we_in,
                        const float* __restrict__ Wfc,
                        const float* __restrict__ bfc) {
    __shared__ float As[64][33];
    __shared__ float Bs[64][33];

    const int tid = threadIdx.x;
    const int tx  = tid & 15;
    const int ty  = tid >> 4;
    const int m0  = blockIdx.y * 64;
    const int k0  = blockIdx.x * 64;

    float acc[4][4];
#pragma unroll
    for (int i = 0; i < 4; i++)
#pragma unroll
        for (int j = 0; j < 4; j++) acc[i][j] = 0.f;

    for (int d0 = 0; d0 < WD; d0 += 32) {
#pragma unroll
        for (int i = tid; i < 64 * 32; i += 256) {
            int r = i >> 5, c = i & 31;
            int m = m0 + r;
            As[r][c] = (m < M_WE) ? we_in[m * WD + d0 + c] : 0.f;
            Bs[r][c] = Wfc[(k0 + r) * WD + d0 + c];
        }
        __syncthreads();
#pragma unroll
        for (int dd = 0; dd < 32; dd++) {
            float a[4], b[4];
#pragma unroll
            for (int i = 0; i < 4; i++) a[i] = As[ty * 4 + i][dd];
#pragma unroll
            for (int j = 0; j < 4; j++) b[j] = Bs[tx * 4 + j][dd];
#pragma unroll
            for (int i = 0; i < 4; i++)
#pragma unroll
                for (int j = 0; j < 4; j++) acc[i][j] += a[i] * b[j];
        }
        __syncthreads();
    }

#pragma unroll
    for (int i = 0; i < 4; i++) {
        int m = m0 + ty * 4 + i;
        if (m < M_WE) {
#pragma unroll
            for (int j = 0; j < 4; j++) {
                int k = k0 + tx * 4 + j;
                g_we[m * HW2 + k] = acc[i][j] + bfc[k];
            }
        }
    }
}

// ---------------------------------------------------------------------------
// Kernel 2: fused  scores -> softmax -> att_feat  per (batch, 64-channel tile)
//   Phase 1: scores[c][n] = sum_k f[b,c,k] * we[b,n,k]   (GEMM 64x80xK=1024)
//   Phase 2: softmax over n (77 valid) in smem
//   Phase 3: out[c][k]   = sum_n att[c][n] * we[b,n,k]    (GEMM 64x1024xK=77)
// ---------------------------------------------------------------------------
__global__ void attn_fused(const float* __restrict__ feat,
                           float* __restrict__ out) {
    // Union buffer: phase1 tiles (As 64x33 + Bs 80x33 = 4752 f) vs
    //               phase3 tile  (Ws 77x64 = 4928 f)
    __shared__ float U[4928];
    __shared__ float S[64 * 81];   // scores / attention weights, padded stride 81

    float* As = U;              // [64][33]
    float* Bs = U + 64 * 33;    // [80][33]
    float* Ws = U;              // [77][64]

    const int tid = threadIdx.x;
    const int tx  = tid & 15;
    const int ty  = tid >> 4;
    const int b   = blockIdx.y;
    const int c0  = blockIdx.x * 64;

    const float* fb  = feat + ((size_t)b * CC + c0) * HW2;
    const float* web = g_we + (size_t)b * NW * HW2;
    float*       ob  = out  + ((size_t)b * CC + c0) * HW2;

    // ---- Phase 1: scores (64 channels x 80 n, n>=77 padded with zeros) ----
    float acc[4][5];
#pragma unroll
    for (int i = 0; i < 4; i++)
#pragma unroll
        for (int j = 0; j < 5; j++) acc[i][j] = 0.f;

    for (int k0 = 0; k0 < HW2; k0 += 32) {
#pragma unroll
        for (int i = tid; i < 64 * 32; i += 256) {
            int r = i >> 5, c = i & 31;
            As[r * 33 + c] = fb[r * HW2 + k0 + c];
        }
#pragma unroll
        for (int i = tid; i < 80 * 32; i += 256) {
            int r = i >> 5, c = i & 31;
            Bs[r * 33 + c] = (r < NW) ? web[r * HW2 + k0 + c] : 0.f;
        }
        __syncthreads();
#pragma unroll
        for (int kk = 0; kk < 32; kk++) {
            float a[4], bn[5];
#pragma unroll
            for (int i = 0; i < 4; i++) a[i] = As[(ty * 4 + i) * 33 + kk];
#pragma unroll
            for (int j = 0; j < 5; j++) bn[j] = Bs[(tx * 5 + j) * 33 + kk];
#pragma unroll
            for (int i = 0; i < 4; i++)
#pragma unroll
                for (int j = 0; j < 5; j++) acc[i][j] += a[i] * bn[j];
        }
        __syncthreads();
    }

    // store scores to smem
#pragma unroll
    for (int i = 0; i < 4; i++)
#pragma unroll
        for (int j = 0; j < 5; j++)
            S[(ty * 4 + i) * 81 + (tx * 5 + j)] = acc[i][j];
    __syncthreads();

    // ---- Phase 2: softmax over n (77) per channel row ----
    if (tid < 64) {
        float* row = S + tid * 81;
        float mx = -1e30f;
        for (int n = 0; n < NW; n++) mx = fmaxf(mx, row[n]);
        float s = 0.f;
        for (int n = 0; n < NW; n++) {
            float e = __expf(row[n] - mx);
            row[n] = e;
            s += e;
        }
        float inv = 1.f / s;
        for (int n = 0; n < NW; n++) row[n] *= inv;
    }
    __syncthreads();

    // ---- Phase 3: att_feat: out[c][k] = sum_n att[c][n] * we[n][k] ----
    for (int kc = 0; kc < HW2; kc += 64) {
        // load we tile [77][64]
        for (int i = tid; i < NW * 64; i += 256) {
            int r = i >> 6, c = i & 63;
            Ws[i] = web[r * HW2 + kc + c];
        }
        __syncthreads();

        float4 acc2[4];
#pragma unroll
        for (int i = 0; i < 4; i++) acc2[i] = make_float4(0.f, 0.f, 0.f, 0.f);

        for (int n = 0; n < NW; n++) {
            float4 wv = *(const float4*)&Ws[n * 64 + tx * 4];
#pragma unroll
            for (int i = 0; i < 4; i++) {
                float a = S[(ty * 4 + i) * 81 + n];
                acc2[i].x += a * wv.x;
                acc2[i].y += a * wv.y;
                acc2[i].z += a * wv.z;
                acc2[i].w += a * wv.w;
            }
        }

#pragma unroll
        for (int i = 0; i < 4; i++) {
            *(float4*)&ob[(ty * 4 + i) * HW2 + kc + tx * 4] = acc2[i];
        }
        __syncthreads();
    }
}

// ---------------------------------------------------------------------------
extern "C" void kernel_launch(void* const* d_in, const int* in_sizes, int n_in,
                              void* d_out, int out_size) {
    const float* feat     = (const float*)d_in[0];   // 32*512*32*32
    const float* word_emb = (const float*)d_in[1];   // 32*77*256
    const float* W_fc     = (const float*)d_in[2];   // 1024*256
    const float* b_fc     = (const float*)d_in[3];   // 1024
    float* out            = (float*)d_out;           // 32*512*1024

    (void)in_sizes; (void)n_in; (void)out_size;

    // Kernel 1: we = word_emb @ W_fc^T + b_fc
    dim3 g1(HW2 / 64, (M_WE + 63) / 64);   // (16, 39)
    we_gemm<<<g1, 256>>>(word_emb, W_fc, b_fc);

    // Kernel 2: fused scores/softmax/att_feat
    dim3 g2(CC / 64, BB);                  // (8, 32)
    attn_fused<<<g2, 256>>>(feat, out);
}

// round 8
// speedup vs baseline: 1.3990x; 1.3864x over previous
#include <cuda_runtime.h>
#include <cuda_bf16.h>
#include <cstdint>

#define BB   32
#define CC   512
#define HW2  1024
#define NW   77
#define NP   80          // padded n
#define WD   256
#define MP   (BB * NP)   // 2560 padded rows

// ---------------- scratch (bf16 splits of we and we^T) ----------------
__device__ __nv_bfloat16 g_we_hi[(size_t)BB * NP * HW2];
__device__ __nv_bfloat16 g_we_lo[(size_t)BB * NP * HW2];
__device__ __nv_bfloat16 g_weT_hi[(size_t)BB * HW2 * NP];
__device__ __nv_bfloat16 g_weT_lo[(size_t)BB * HW2 * NP];

// ---------------- warp-MMA helpers (sm_80+; works on plain sm_103) ----------
__device__ __forceinline__ uint32_t smem_to_u32(const void* p) {
    uint32_t a;
    asm("{ .reg .u64 t; cvta.to.shared.u64 t, %1; cvt.u32.u64 %0, t; }" : "=r"(a) : "l"(p));
    return a;
}

__device__ __forceinline__ void mma_bf16(float* c, const uint32_t* a, const uint32_t* b) {
    asm volatile(
        "mma.sync.aligned.m16n8k16.row.col.f32.bf16.bf16.f32 "
        "{%0,%1,%2,%3}, {%4,%5,%6,%7}, {%8,%9}, {%0,%1,%2,%3};"
        : "+f"(c[0]), "+f"(c[1]), "+f"(c[2]), "+f"(c[3])
        : "r"(a[0]), "r"(a[1]), "r"(a[2]), "r"(a[3]), "r"(b[0]), "r"(b[1]));
}
__device__ __forceinline__ void ldsm4(uint32_t* r, uint32_t addr) {
    asm volatile("ldmatrix.sync.aligned.m8n8.x4.shared.b16 {%0,%1,%2,%3}, [%4];"
        : "=r"(r[0]), "=r"(r[1]), "=r"(r[2]), "=r"(r[3]) : "r"(addr));
}
__device__ __forceinline__ void ldsm2(uint32_t* r, uint32_t addr) {
    asm volatile("ldmatrix.sync.aligned.m8n8.x2.shared.b16 {%0,%1}, [%2];"
        : "=r"(r[0]), "=r"(r[1]) : "r"(addr));
}

// pack (v0 -> low half, v1 -> high half) into hi/lo bf16 split words
__device__ __forceinline__ void split2(float v0, float v1, uint32_t& ph, uint32_t& pl) {
    __nv_bfloat16 h0 = __float2bfloat16(v0), h1 = __float2bfloat16(v1);
    float r0 = v0 - __bfloat162float(h0), r1 = v1 - __bfloat162float(h1);
    __nv_bfloat16 l0 = __float2bfloat16(r0), l1 = __float2bfloat16(r1);
    ph = (uint32_t)__bfloat16_as_ushort(h0) | ((uint32_t)__bfloat16_as_ushort(h1) << 16);
    pl = (uint32_t)__bfloat16_as_ushort(l0) | ((uint32_t)__bfloat16_as_ushort(l1) << 16);
}

// ---------------------------------------------------------------------------
// Kernel 1: we = word_emb @ W_fc^T + b_fc  (SIMT fp32) -> bf16 hi/lo splits,
// padded to n=80 rows per batch (rows 77..79 zero).
// ---------------------------------------------------------------------------
__global__ void we_gemm(const float* __restrict__ we_in,
                        const float* __restrict__ Wfc,
                        const float* __restrict__ bfc) {
    __shared__ float As[64][33];
    __shared__ float Bs[64][33];

    const int tid = threadIdx.x;
    const int tx  = tid & 15;
    const int ty  = tid >> 4;
    const int m0  = blockIdx.y * 64;
    const int k0  = blockIdx.x * 64;

    float acc[4][4];
#pragma unroll
    for (int i = 0; i < 4; i++)
#pragma unroll
        for (int j = 0; j < 4; j++) acc[i][j] = 0.f;

    for (int d0 = 0; d0 < WD; d0 += 32) {
#pragma unroll
        for (int i = tid; i < 64 * 32; i += 256) {
            int r = i >> 5, c = i & 31;
            int mp = m0 + r;
            int bb = mp / NP, nn = mp % NP;
            As[r][c] = (nn < NW) ? we_in[((size_t)bb * NW + nn) * WD + d0 + c] : 0.f;
            Bs[r][c] = Wfc[(size_t)(k0 + r) * WD + d0 + c];
        }
        __syncthreads();
#pragma unroll
        for (int dd = 0; dd < 32; dd++) {
            float a[4], b[4];
#pragma unroll
            for (int i = 0; i < 4; i++) a[i] = As[ty * 4 + i][dd];
#pragma unroll
            for (int j = 0; j < 4; j++) b[j] = Bs[tx * 4 + j][dd];
#pragma unroll
            for (int i = 0; i < 4; i++)
#pragma unroll
                for (int j = 0; j < 4; j++) acc[i][j] += a[i] * b[j];
        }
        __syncthreads();
    }

#pragma unroll
    for (int i = 0; i < 4; i++) {
        int mp = m0 + ty * 4 + i;
        int nn = mp % NP;
#pragma unroll
        for (int j = 0; j < 4; j++) {
            int k = k0 + tx * 4 + j;
            float v = (nn < NW) ? (acc[i][j] + bfc[k]) : 0.f;
            __nv_bfloat16 h = __float2bfloat16(v);
            float r = v - __bfloat162float(h);
            g_we_hi[(size_t)mp * HW2 + k] = h;
            g_we_lo[(size_t)mp * HW2 + k] = __float2bfloat16(r);
        }
    }
}

// ---------------------------------------------------------------------------
// Kernel 2: transpose splits -> weT[b][k][n] (n padded to 80)
// ---------------------------------------------------------------------------
__global__ void transpose_we() {
    __shared__ unsigned short sh[NP][66];
    __shared__ unsigned short sl[NP][66];
    const int tid = threadIdx.x;
    const int k0  = blockIdx.x * 64;
    const int b   = blockIdx.y;

    for (int i = tid; i < NP * 32; i += 256) {
        int n = i >> 5, w = i & 31;
        uint32_t vh = *(const uint32_t*)(g_we_hi + ((size_t)b * NP + n) * HW2 + k0 + 2 * w);
        uint32_t vl = *(const uint32_t*)(g_we_lo + ((size_t)b * NP + n) * HW2 + k0 + 2 * w);
        sh[n][2 * w] = (unsigned short)(vh & 0xffff); sh[n][2 * w + 1] = (unsigned short)(vh >> 16);
        sl[n][2 * w] = (unsigned short)(vl & 0xffff); sl[n][2 * w + 1] = (unsigned short)(vl >> 16);
    }
    __syncthreads();
    for (int i = tid; i < 64 * 40; i += 256) {
        int k = i / 40, j = i % 40;
        uint32_t oh = (uint32_t)sh[2 * j][k] | ((uint32_t)sh[2 * j + 1][k] << 16);
        uint32_t ol = (uint32_t)sl[2 * j][k] | ((uint32_t)sl[2 * j + 1][k] << 16);
        size_t off = ((size_t)b * HW2 + k0 + k) * NP;
        *(uint32_t*)(g_weT_hi + off + 2 * j) = oh;
        *(uint32_t*)(g_weT_lo + off + 2 * j) = ol;
    }
}

// ---------------------------------------------------------------------------
// Kernel 3: fused warp-MMA attention per (batch, 128-channel tile)
//   Phase 1: scores[128][80] via m16n8k16 bf16, 3-term split, fp32 reg accum
//   Phase 2: register softmax (rows live in lane quads)
//   Phase 3: att (repacked in-register as A-fragments) @ weT  -> out
// ---------------------------------------------------------------------------
// smem layout (bytes), phase1:  A hi/lo [128][72]b16, B hi/lo [80][72]b16
#define AH_OFF 0
#define AL_OFF 18432
#define BH_OFF 36864
#define BL_OFF 48384
#define SMEM_SZ 59904
// phase3 union:  W hi/lo [128][88]b16
#define WH_OFF 0
#define WL_OFF 22528
#define SA 144   // A/B row stride bytes (72 bf16)
#define SW 176   // W row stride bytes (88 bf16)

__global__ __launch_bounds__(256, 1) void attn_tc(const float* __restrict__ feat,
                                                  float* __restrict__ out) {
    extern __shared__ char smem[];
    const uint32_t sb = smem_to_u32(smem);
    const int tid  = threadIdx.x;
    const int wid  = tid >> 5;
    const int lane = tid & 31;
    const int q    = lane & 3;
    const int g    = lane >> 2;
    const int b    = blockIdx.y;
    const int c0   = blockIdx.x * 128;
    const int r0   = wid * 16;            // warp's 16 channel rows

    const float* fb = feat + ((size_t)b * CC + c0) * HW2;
    const __nv_bfloat16* weh = g_we_hi + (size_t)b * NP * HW2;
    const __nv_bfloat16* wel = g_we_lo + (size_t)b * NP * HW2;

    // ================= Phase 1: scores = f . we^T (K=1024) ===================
    float acc[10][4];
#pragma unroll
    for (int t = 0; t < 10; t++)
#pragma unroll
        for (int j = 0; j < 4; j++) acc[t][j] = 0.f;

    // per-lane ldmatrix base addresses
    const int am = lane >> 3;                 // matrix id 0..3 (x4)
    const int ar = lane & 7;
    const uint32_t aoff = (uint32_t)((r0 + (am & 1) * 8 + ar) * SA + (am >> 1) * 16);
    const uint32_t aaddr_h = sb + AH_OFF + aoff;
    const uint32_t aaddr_l = sb + AL_OFF + aoff;
    const uint32_t boff = (uint32_t)(ar * SA + ((lane >> 3) & 1) * 16);
    const uint32_t baddr_h = sb + BH_OFF + boff;
    const uint32_t baddr_l = sb + BL_OFF + boff;

    for (int ch = 0; ch < 16; ch++) {
        const int kc = ch * 64;
        // --- A tile: 128 rows x 64 cols fp32 -> bf16 hi/lo ---
        {
            const int r = tid >> 1, h = tid & 1;
            const float* src = fb + (size_t)r * HW2 + kc + h * 32;
            char* ph_ = smem + AH_OFF + r * SA + h * 64;
            char* pl_ = smem + AL_OFF + r * SA + h * 64;
#pragma unroll
            for (int i = 0; i < 8; i++) {
                float4 v = *(const float4*)(src + i * 4);
                uint32_t p0h, p0l, p1h, p1l;
                split2(v.x, v.y, p0h, p0l);
                split2(v.z, v.w, p1h, p1l);
                *(uint32_t*)(ph_ + i * 8)     = p0h;
                *(uint32_t*)(ph_ + i * 8 + 4) = p1h;
                *(uint32_t*)(pl_ + i * 8)     = p0l;
                *(uint32_t*)(pl_ + i * 8 + 4) = p1l;
            }
        }
        // --- B tile: 80 rows x 64 cols bf16 hi/lo ---
        for (int i = tid; i < NP * 32; i += 256) {
            int n = i >> 5, w = i & 31;
            *(uint32_t*)(smem + BH_OFF + n * SA + w * 4) =
                *(const uint32_t*)(weh + (size_t)n * HW2 + kc + 2 * w);
            *(uint32_t*)(smem + BL_OFF + n * SA + w * 4) =
                *(const uint32_t*)(wel + (size_t)n * HW2 + kc + 2 * w);
        }
        __syncthreads();

#pragma unroll
        for (int ks = 0; ks < 4; ks++) {
            const uint32_t kb = ks * 32;       // 16 cols * 2B
            uint32_t a_h[4], a_l[4];
            ldsm4(a_h, aaddr_h + kb);
            ldsm4(a_l, aaddr_l + kb);
#pragma unroll
            for (int t = 0; t < 10; t++) {
                uint32_t bh[2], bl[2];
                ldsm2(bh, baddr_h + t * 8 * SA + kb);
                ldsm2(bl, baddr_l + t * 8 * SA + kb);
                mma_bf16(acc[t], a_h, bh);
                mma_bf16(acc[t], a_h, bl);
                mma_bf16(acc[t], a_l, bh);
            }
        }
        __syncthreads();
    }

    // ================= Phase 2: register softmax =============================
    // C layout: c0,c1 -> row r0+g cols 8t+2q,+1 ; c2,c3 -> row r0+g+8
    float mx0 = -1e30f, mx1 = -1e30f;
#pragma unroll
    for (int t = 0; t < 10; t++) {
        int col = t * 8 + 2 * q;
        if (col < NW)     { mx0 = fmaxf(mx0, acc[t][0]); mx1 = fmaxf(mx1, acc[t][2]); }
        if (col + 1 < NW) { mx0 = fmaxf(mx0, acc[t][1]); mx1 = fmaxf(mx1, acc[t][3]); }
    }
    mx0 = fmaxf(mx0, __shfl_xor_sync(0xffffffffu, mx0, 1));
    mx0 = fmaxf(mx0, __shfl_xor_sync(0xffffffffu, mx0, 2));
    mx1 = fmaxf(mx1, __shfl_xor_sync(0xffffffffu, mx1, 1));
    mx1 = fmaxf(mx1, __shfl_xor_sync(0xffffffffu, mx1, 2));
    float s0 = 0.f, s1 = 0.f;
#pragma unroll
    for (int t = 0; t < 10; t++) {
        int col = t * 8 + 2 * q;
        float e0 = (col < NW)     ? __expf(acc[t][0] - mx0) : 0.f;
        float e1 = (col + 1 < NW) ? __expf(acc[t][1] - mx0) : 0.f;
        float e2 = (col < NW)     ? __expf(acc[t][2] - mx1) : 0.f;
        float e3 = (col + 1 < NW) ? __expf(acc[t][3] - mx1) : 0.f;
        acc[t][0] = e0; acc[t][1] = e1; acc[t][2] = e2; acc[t][3] = e3;
        s0 += e0 + e1; s1 += e2 + e3;
    }
    s0 += __shfl_xor_sync(0xffffffffu, s0, 1);
    s0 += __shfl_xor_sync(0xffffffffu, s0, 2);
    s1 += __shfl_xor_sync(0xffffffffu, s1, 1);
    s1 += __shfl_xor_sync(0xffffffffu, s1, 2);
    const float inv0 = 1.f / s0, inv1 = 1.f / s1;

    // Repack att into bf16 A-fragments (C layout == A-fragment layout)
    uint32_t att_h[5][4], att_l[5][4];
#pragma unroll
    for (int s = 0; s < 5; s++) {
        split2(acc[2 * s][0] * inv0,     acc[2 * s][1] * inv0,     att_h[s][0], att_l[s][0]);
        split2(acc[2 * s][2] * inv1,     acc[2 * s][3] * inv1,     att_h[s][1], att_l[s][1]);
        split2(acc[2 * s + 1][0] * inv0, acc[2 * s + 1][1] * inv0, att_h[s][2], att_l[s][2]);
        split2(acc[2 * s + 1][2] * inv1, acc[2 * s + 1][3] * inv1, att_h[s][3], att_l[s][3]);
    }
    __syncthreads();

    // ================= Phase 3: out = att @ weT (8 chunks of 128 cols) =======
    const uint32_t wboff = (uint32_t)((lane & 7) * SW + ((lane >> 3) & 1) * 16);
    for (int oc = 0; oc < 8; oc++) {
        const int k0 = oc * 128;
        const __nv_bfloat16* th = g_weT_hi + ((size_t)b * HW2 + k0) * NP;
        const __nv_bfloat16* tl = g_weT_lo + ((size_t)b * HW2 + k0) * NP;
        for (int i = tid; i < 128 * 40; i += 256) {
            int r = i / 40, w = i % 40;
            *(uint32_t*)(smem + WH_OFF + r * SW + w * 4) =
                *(const uint32_t*)(th + (size_t)r * NP + 2 * w);
            *(uint32_t*)(smem + WL_OFF + r * SW + w * 4) =
                *(const uint32_t*)(tl + (size_t)r * NP + 2 * w);
        }
        __syncthreads();

        float acc2[16][4];
#pragma unroll
        for (int t = 0; t < 16; t++)
#pragma unroll
            for (int j = 0; j < 4; j++) acc2[t][j] = 0.f;

        const uint32_t wh_base = sb + WH_OFF + wboff;
        const uint32_t wl_base = sb + WL_OFF + wboff;
#pragma unroll
        for (int kt = 0; kt < 16; kt++) {
#pragma unroll
            for (int ks = 0; ks < 5; ks++) {
                uint32_t bh[2], bl[2];
                ldsm2(bh, wh_base + kt * 8 * SW + ks * 32);
                ldsm2(bl, wl_base + kt * 8 * SW + ks * 32);
                mma_bf16(acc2[kt], att_h[ks], bh);
                mma_bf16(acc2[kt], att_h[ks], bl);
                mma_bf16(acc2[kt], att_l[ks], bh);
            }
        }

        float* ob = out + ((size_t)b * CC + c0 + r0) * HW2 + k0;
#pragma unroll
        for (int kt = 0; kt < 16; kt++) {
            int col = kt * 8 + 2 * q;
            *(float2*)&ob[(size_t)g * HW2 + col]       = make_float2(acc2[kt][0], acc2[kt][1]);
            *(float2*)&ob[(size_t)(g + 8) * HW2 + col] = make_float2(acc2[kt][2], acc2[kt][3]);
        }
        __syncthreads();
    }
}

// ---------------------------------------------------------------------------
extern "C" void kernel_launch(void* const* d_in, const int* in_sizes, int n_in,
                              void* d_out, int out_size) {
    const float* feat     = (const float*)d_in[0];
    const float* word_emb = (const float*)d_in[1];
    const float* W_fc     = (const float*)d_in[2];
    const float* b_fc     = (const float*)d_in[3];
    float* out            = (float*)d_out;
    (void)in_sizes; (void)n_in; (void)out_size;

    cudaFuncSetAttribute(attn_tc, cudaFuncAttributeMaxDynamicSharedMemorySize, SMEM_SZ);

    we_gemm<<<dim3(HW2 / 64, MP / 64), 256>>>(word_emb, W_fc, b_fc);  // (16, 40)
    transpose_we<<<dim3(HW2 / 64, BB), 256>>>();                      // (16, 32)
    attn_tc<<<dim3(CC / 128, BB), 256, SMEM_SZ>>>(feat, out);         // (4, 32)
}

// round 9
// speedup vs baseline: 1.6196x; 1.1577x over previous
#include <cuda_runtime.h>
#include <cuda_bf16.h>
#include <cstdint>

#define BB   32
#define CC   512
#define HW2  1024
#define NW   77
#define NP   80          // padded n
#define WD   256
#define MP   (BB * NP)   // 2560 padded rows

// ---------------- scratch (bf16 splits of we and we^T) ----------------
__device__ __nv_bfloat16 g_we_hi[(size_t)BB * NP * HW2];
__device__ __nv_bfloat16 g_we_lo[(size_t)BB * NP * HW2];
__device__ __nv_bfloat16 g_weT_hi[(size_t)BB * HW2 * NP];
__device__ __nv_bfloat16 g_weT_lo[(size_t)BB * HW2 * NP];

// ---------------- warp-MMA helpers (sm_80+; works on plain sm_103) ----------
__device__ __forceinline__ uint32_t smem_to_u32(const void* p) {
    uint32_t a;
    asm("{ .reg .u64 t; cvta.to.shared.u64 t, %1; cvt.u32.u64 %0, t; }" : "=r"(a) : "l"(p));
    return a;
}

__device__ __forceinline__ void mma_bf16(float* c, const uint32_t* a, const uint32_t* b) {
    asm volatile(
        "mma.sync.aligned.m16n8k16.row.col.f32.bf16.bf16.f32 "
        "{%0,%1,%2,%3}, {%4,%5,%6,%7}, {%8,%9}, {%0,%1,%2,%3};"
        : "+f"(c[0]), "+f"(c[1]), "+f"(c[2]), "+f"(c[3])
        : "r"(a[0]), "r"(a[1]), "r"(a[2]), "r"(a[3]), "r"(b[0]), "r"(b[1]));
}
__device__ __forceinline__ void ldsm4(uint32_t* r, uint32_t addr) {
    asm volatile("ldmatrix.sync.aligned.m8n8.x4.shared.b16 {%0,%1,%2,%3}, [%4];"
        : "=r"(r[0]), "=r"(r[1]), "=r"(r[2]), "=r"(r[3]) : "r"(addr));
}
__device__ __forceinline__ void ldsm2(uint32_t* r, uint32_t addr) {
    asm volatile("ldmatrix.sync.aligned.m8n8.x2.shared.b16 {%0,%1}, [%2];"
        : "=r"(r[0]), "=r"(r[1]) : "r"(addr));
}

// pack (v0 -> low half, v1 -> high half) into hi/lo bf16 split words
__device__ __forceinline__ void split2(float v0, float v1, uint32_t& ph, uint32_t& pl) {
    __nv_bfloat16 h0 = __float2bfloat16(v0), h1 = __float2bfloat16(v1);
    float r0 = v0 - __bfloat162float(h0), r1 = v1 - __bfloat162float(h1);
    __nv_bfloat16 l0 = __float2bfloat16(r0), l1 = __float2bfloat16(r1);
    ph = (uint32_t)__bfloat16_as_ushort(h0) | ((uint32_t)__bfloat16_as_ushort(h1) << 16);
    pl = (uint32_t)__bfloat16_as_ushort(l0) | ((uint32_t)__bfloat16_as_ushort(l1) << 16);
}

#define SA 144   // bf16 tile row stride bytes (72 bf16: 64 data + 8 pad)
#define SW 176   // phase-3 W row stride bytes (88 bf16)

// ---------------------------------------------------------------------------
// Kernel 1 (tensorized): we = word_emb @ W_fc^T + b_fc -> bf16 hi/lo splits.
// GEMM M=2560(padded rows) x N=1024 x K=256. CTA tile 128x128, 8 warps,
// each warp 16 rows x 128 cols, acc[16][4], 3-term bf16 split on HMMA.
// ---------------------------------------------------------------------------
#define G1_AH 0
#define G1_AL 18432
#define G1_BH 36864
#define G1_BL 55296
#define G1_SMEM 73728

__global__ __launch_bounds__(256, 1) void we_gemm_tc(const float* __restrict__ we_in,
                                                     const float* __restrict__ Wfc,
                                                     const float* __restrict__ bfc) {
    extern __shared__ char smem[];
    const uint32_t sb = smem_to_u32(smem);
    const int tid  = threadIdx.x;
    const int wid  = tid >> 5;
    const int lane = tid & 31;
    const int q    = lane & 3;
    const int g    = lane >> 2;
    const int m0   = blockIdx.y * 128;
    const int k0   = blockIdx.x * 128;
    const int r0   = wid * 16;

    float acc[16][4];
#pragma unroll
    for (int t = 0; t < 16; t++)
#pragma unroll
        for (int j = 0; j < 4; j++) acc[t][j] = 0.f;

    // ldmatrix lane addresses
    const int am = lane >> 3;
    const int ar = lane & 7;
    const uint32_t aoff = (uint32_t)((r0 + (am & 1) * 8 + ar) * SA + (am >> 1) * 16);
    const uint32_t aaddr_h = sb + G1_AH + aoff;
    const uint32_t aaddr_l = sb + G1_AL + aoff;
    const uint32_t boff = (uint32_t)(ar * SA + ((lane >> 3) & 1) * 16);
    const uint32_t baddr_h = sb + G1_BH + boff;
    const uint32_t baddr_l = sb + G1_BL + boff;

    // loader lane mapping: 2 threads per row, 32 cols each
    const int lr = tid >> 1, lh = tid & 1;
    const int mp_l = m0 + lr;
    const int bb_l = mp_l / NP, nn_l = mp_l % NP;
    const bool a_valid = (nn_l < NW);
    const float* asrc = we_in + ((size_t)bb_l * NW + nn_l) * WD + lh * 32;
    const float* bsrc = Wfc + (size_t)(k0 + lr) * WD + lh * 32;

    for (int ch = 0; ch < 4; ch++) {
        const int dc = ch * 64;
        // --- A tile: word_emb rows (padded) 128 x 64 fp32 -> hi/lo ---
        {
            char* ph_ = smem + G1_AH + lr * SA + lh * 64;
            char* pl_ = smem + G1_AL + lr * SA + lh * 64;
#pragma unroll
            for (int i = 0; i < 8; i++) {
                float4 v = a_valid ? *(const float4*)(asrc + dc + i * 4)
                                   : make_float4(0.f, 0.f, 0.f, 0.f);
                uint32_t p0h, p0l, p1h, p1l;
                split2(v.x, v.y, p0h, p0l);
                split2(v.z, v.w, p1h, p1l);
                *(uint32_t*)(ph_ + i * 8)     = p0h;
                *(uint32_t*)(ph_ + i * 8 + 4) = p1h;
                *(uint32_t*)(pl_ + i * 8)     = p0l;
                *(uint32_t*)(pl_ + i * 8 + 4) = p1l;
            }
        }
        // --- B tile: W_fc rows 128 x 64 fp32 -> hi/lo ---
        {
            char* ph_ = smem + G1_BH + lr * SA + lh * 64;
            char* pl_ = smem + G1_BL + lr * SA + lh * 64;
#pragma unroll
            for (int i = 0; i < 8; i++) {
                float4 v = *(const float4*)(bsrc + dc + i * 4);
                uint32_t p0h, p0l, p1h, p1l;
                split2(v.x, v.y, p0h, p0l);
                split2(v.z, v.w, p1h, p1l);
                *(uint32_t*)(ph_ + i * 8)     = p0h;
                *(uint32_t*)(ph_ + i * 8 + 4) = p1h;
                *(uint32_t*)(pl_ + i * 8)     = p0l;
                *(uint32_t*)(pl_ + i * 8 + 4) = p1l;
            }
        }
        __syncthreads();

#pragma unroll
        for (int ks = 0; ks < 4; ks++) {
            const uint32_t kb = ks * 32;
            uint32_t a_h[4], a_l[4];
            ldsm4(a_h, aaddr_h + kb);
            ldsm4(a_l, aaddr_l + kb);
#pragma unroll
            for (int t = 0; t < 16; t++) {
                uint32_t bh[2], bl[2];
                ldsm2(bh, baddr_h + t * 8 * SA + kb);
                ldsm2(bl, baddr_l + t * 8 * SA + kb);
                mma_bf16(acc[t], a_h, bh);
                mma_bf16(acc[t], a_h, bl);
                mma_bf16(acc[t], a_l, bh);
            }
        }
        __syncthreads();
    }

    // --- epilogue: bias, zero padded rows, split to bf16 hi/lo ---
    const int mp0 = m0 + r0 + g;
    const int mp1 = mp0 + 8;
    const bool v0ok = ((mp0 % NP) < NW);
    const bool v1ok = ((mp1 % NP) < NW);
#pragma unroll
    for (int t = 0; t < 16; t++) {
        const int col = k0 + t * 8 + 2 * q;
        const float b0 = bfc[col], b1 = bfc[col + 1];
        float v00 = v0ok ? acc[t][0] + b0 : 0.f;
        float v01 = v0ok ? acc[t][1] + b1 : 0.f;
        float v10 = v1ok ? acc[t][2] + b0 : 0.f;
        float v11 = v1ok ? acc[t][3] + b1 : 0.f;
        uint32_t ph, pl;
        split2(v00, v01, ph, pl);
        *(uint32_t*)(g_we_hi + (size_t)mp0 * HW2 + col) = ph;
        *(uint32_t*)(g_we_lo + (size_t)mp0 * HW2 + col) = pl;
        split2(v10, v11, ph, pl);
        *(uint32_t*)(g_we_hi + (size_t)mp1 * HW2 + col) = ph;
        *(uint32_t*)(g_we_lo + (size_t)mp1 * HW2 + col) = pl;
    }
}

// ---------------------------------------------------------------------------
// Kernel 2: transpose splits -> weT[b][k][n] (n padded to 80)
// ---------------------------------------------------------------------------
__global__ void transpose_we() {
    __shared__ unsigned short sh[NP][66];
    __shared__ unsigned short sl[NP][66];
    const int tid = threadIdx.x;
    const int k0  = blockIdx.x * 64;
    const int b   = blockIdx.y;

    for (int i = tid; i < NP * 32; i += 256) {
        int n = i >> 5, w = i & 31;
        uint32_t vh = *(const uint32_t*)(g_we_hi + ((size_t)b * NP + n) * HW2 + k0 + 2 * w);
        uint32_t vl = *(const uint32_t*)(g_we_lo + ((size_t)b * NP + n) * HW2 + k0 + 2 * w);
        sh[n][2 * w] = (unsigned short)(vh & 0xffff); sh[n][2 * w + 1] = (unsigned short)(vh >> 16);
        sl[n][2 * w] = (unsigned short)(vl & 0xffff); sl[n][2 * w + 1] = (unsigned short)(vl >> 16);
    }
    __syncthreads();
    for (int i = tid; i < 64 * 40; i += 256) {
        int k = i / 40, j = i % 40;
        uint32_t oh = (uint32_t)sh[2 * j][k] | ((uint32_t)sh[2 * j + 1][k] << 16);
        uint32_t ol = (uint32_t)sl[2 * j][k] | ((uint32_t)sl[2 * j + 1][k] << 16);
        size_t off = ((size_t)b * HW2 + k0 + k) * NP;
        *(uint32_t*)(g_weT_hi + off + 2 * j) = oh;
        *(uint32_t*)(g_weT_lo + off + 2 * j) = ol;
    }
}

// ---------------------------------------------------------------------------
// Kernel 3: fused warp-MMA attention per (batch, 128-channel tile)
// ---------------------------------------------------------------------------
#define AH_OFF 0
#define AL_OFF 18432
#define BH_OFF 36864
#define BL_OFF 48384
#define SMEM_SZ 59904
#define WH_OFF 0
#define WL_OFF 22528

__global__ __launch_bounds__(256, 1) void attn_tc(const float* __restrict__ feat,
                                                  float* __restrict__ out) {
    extern __shared__ char smem[];
    const uint32_t sb = smem_to_u32(smem);
    const int tid  = threadIdx.x;
    const int wid  = tid >> 5;
    const int lane = tid & 31;
    const int q    = lane & 3;
    const int g    = lane >> 2;
    const int b    = blockIdx.y;
    const int c0   = blockIdx.x * 128;
    const int r0   = wid * 16;

    const float* fb = feat + ((size_t)b * CC + c0) * HW2;
    const __nv_bfloat16* weh = g_we_hi + (size_t)b * NP * HW2;
    const __nv_bfloat16* wel = g_we_lo + (size_t)b * NP * HW2;

    // ================= Phase 1: scores = f . we^T (K=1024) ===================
    float acc[10][4];
#pragma unroll
    for (int t = 0; t < 10; t++)
#pragma unroll
        for (int j = 0; j < 4; j++) acc[t][j] = 0.f;

    const int am = lane >> 3;
    const int ar = lane & 7;
    const uint32_t aoff = (uint32_t)((r0 + (am & 1) * 8 + ar) * SA + (am >> 1) * 16);
    const uint32_t aaddr_h = sb + AH_OFF + aoff;
    const uint32_t aaddr_l = sb + AL_OFF + aoff;
    const uint32_t boff = (uint32_t)(ar * SA + ((lane >> 3) & 1) * 16);
    const uint32_t baddr_h = sb + BH_OFF + boff;
    const uint32_t baddr_l = sb + BL_OFF + boff;

    for (int ch = 0; ch < 16; ch++) {
        const int kc = ch * 64;
        {
            const int r = tid >> 1, h = tid & 1;
            const float* src = fb + (size_t)r * HW2 + kc + h * 32;
            char* ph_ = smem + AH_OFF + r * SA + h * 64;
            char* pl_ = smem + AL_OFF + r * SA + h * 64;
#pragma unroll
            for (int i = 0; i < 8; i++) {
                float4 v = *(const float4*)(src + i * 4);
                uint32_t p0h, p0l, p1h, p1l;
                split2(v.x, v.y, p0h, p0l);
                split2(v.z, v.w, p1h, p1l);
                *(uint32_t*)(ph_ + i * 8)     = p0h;
                *(uint32_t*)(ph_ + i * 8 + 4) = p1h;
                *(uint32_t*)(pl_ + i * 8)     = p0l;
                *(uint32_t*)(pl_ + i * 8 + 4) = p1l;
            }
        }
        for (int i = tid; i < NP * 32; i += 256) {
            int n = i >> 5, w = i & 31;
            *(uint32_t*)(smem + BH_OFF + n * SA + w * 4) =
                *(const uint32_t*)(weh + (size_t)n * HW2 + kc + 2 * w);
            *(uint32_t*)(smem + BL_OFF + n * SA + w * 4) =
                *(const uint32_t*)(wel + (size_t)n * HW2 + kc + 2 * w);
        }
        __syncthreads();

#pragma unroll
        for (int ks = 0; ks < 4; ks++) {
            const uint32_t kb = ks * 32;
            uint32_t a_h[4], a_l[4];
            ldsm4(a_h, aaddr_h + kb);
            ldsm4(a_l, aaddr_l + kb);
#pragma unroll
            for (int t = 0; t < 10; t++) {
                uint32_t bh[2], bl[2];
                ldsm2(bh, baddr_h + t * 8 * SA + kb);
                ldsm2(bl, baddr_l + t * 8 * SA + kb);
                mma_bf16(acc[t], a_h, bh);
                mma_bf16(acc[t], a_h, bl);
                mma_bf16(acc[t], a_l, bh);
            }
        }
        __syncthreads();
    }

    // ================= Phase 2: register softmax =============================
    float mx0 = -1e30f, mx1 = -1e30f;
#pragma unroll
    for (int t = 0; t < 10; t++) {
        int col = t * 8 + 2 * q;
        if (col < NW)     { mx0 = fmaxf(mx0, acc[t][0]); mx1 = fmaxf(mx1, acc[t][2]); }
        if (col + 1 < NW) { mx0 = fmaxf(mx0, acc[t][1]); mx1 = fmaxf(mx1, acc[t][3]); }
    }
    mx0 = fmaxf(mx0, __shfl_xor_sync(0xffffffffu, mx0, 1));
    mx0 = fmaxf(mx0, __shfl_xor_sync(0xffffffffu, mx0, 2));
    mx1 = fmaxf(mx1, __shfl_xor_sync(0xffffffffu, mx1, 1));
    mx1 = fmaxf(mx1, __shfl_xor_sync(0xffffffffu, mx1, 2));
    float s0 = 0.f, s1 = 0.f;
#pragma unroll
    for (int t = 0; t < 10; t++) {
        int col = t * 8 + 2 * q;
        float e0 = (col < NW)     ? __expf(acc[t][0] - mx0) : 0.f;
        float e1 = (col + 1 < NW) ? __expf(acc[t][1] - mx0) : 0.f;
        float e2 = (col < NW)     ? __expf(acc[t][2] - mx1) : 0.f;
        float e3 = (col + 1 < NW) ? __expf(acc[t][3] - mx1) : 0.f;
        acc[t][0] = e0; acc[t][1] = e1; acc[t][2] = e2; acc[t][3] = e3;
        s0 += e0 + e1; s1 += e2 + e3;
    }
    s0 += __shfl_xor_sync(0xffffffffu, s0, 1);
    s0 += __shfl_xor_sync(0xffffffffu, s0, 2);
    s1 += __shfl_xor_sync(0xffffffffu, s1, 1);
    s1 += __shfl_xor_sync(0xffffffffu, s1, 2);
    const float inv0 = 1.f / s0, inv1 = 1.f / s1;

    uint32_t att_h[5][4], att_l[5][4];
#pragma unroll
    for (int s = 0; s < 5; s++) {
        split2(acc[2 * s][0] * inv0,     acc[2 * s][1] * inv0,     att_h[s][0], att_l[s][0]);
        split2(acc[2 * s][2] * inv1,     acc[2 * s][3] * inv1,     att_h[s][1], att_l[s][1]);
        split2(acc[2 * s + 1][0] * inv0, acc[2 * s + 1][1] * inv0, att_h[s][2], att_l[s][2]);
        split2(acc[2 * s + 1][2] * inv1, acc[2 * s + 1][3] * inv1, att_h[s][3], att_l[s][3]);
    }
    __syncthreads();

    // ================= Phase 3: out = att @ weT (8 chunks of 128 cols) =======
    const uint32_t wboff = (uint32_t)((lane & 7) * SW + ((lane >> 3) & 1) * 16);
    for (int oc = 0; oc < 8; oc++) {
        const int k0 = oc * 128;
        const __nv_bfloat16* th = g_weT_hi + ((size_t)b * HW2 + k0) * NP;
        const __nv_bfloat16* tl = g_weT_lo + ((size_t)b * HW2 + k0) * NP;
        for (int i = tid; i < 128 * 40; i += 256) {
            int r = i / 40, w = i % 40;
            *(uint32_t*)(smem + WH_OFF + r * SW + w * 4) =
                *(const uint32_t*)(th + (size_t)r * NP + 2 * w);
            *(uint32_t*)(smem + WL_OFF + r * SW + w * 4) =
                *(const uint32_t*)(tl + (size_t)r * NP + 2 * w);
        }
        __syncthreads();

        float acc2[16][4];
#pragma unroll
        for (int t = 0; t < 16; t++)
#pragma unroll
            for (int j = 0; j < 4; j++) acc2[t][j] = 0.f;

        const uint32_t wh_base = sb + WH_OFF + wboff;
        const uint32_t wl_base = sb + WL_OFF + wboff;
#pragma unroll
        for (int kt = 0; kt < 16; kt++) {
#pragma unroll
            for (int ks = 0; ks < 5; ks++) {
                uint32_t bh[2], bl[2];
                ldsm2(bh, wh_base + kt * 8 * SW + ks * 32);
                ldsm2(bl, wl_base + kt * 8 * SW + ks * 32);
                mma_bf16(acc2[kt], att_h[ks], bh);
                mma_bf16(acc2[kt], att_h[ks], bl);
                mma_bf16(acc2[kt], att_l[ks], bh);
            }
        }

        float* ob = out + ((size_t)b * CC + c0 + r0) * HW2 + k0;
#pragma unroll
        for (int kt = 0; kt < 16; kt++) {
            int col = kt * 8 + 2 * q;
            *(float2*)&ob[(size_t)g * HW2 + col]       = make_float2(acc2[kt][0], acc2[kt][1]);
            *(float2*)&ob[(size_t)(g + 8) * HW2 + col] = make_float2(acc2[kt][2], acc2[kt][3]);
        }
        __syncthreads();
    }
}

// ---------------------------------------------------------------------------
extern "C" void kernel_launch(void* const* d_in, const int* in_sizes, int n_in,
                              void* d_out, int out_size) {
    const float* feat     = (const float*)d_in[0];
    const float* word_emb = (const float*)d_in[1];
    const float* W_fc     = (const float*)d_in[2];
    const float* b_fc     = (const float*)d_in[3];
    float* out            = (float*)d_out;
    (void)in_sizes; (void)n_in; (void)out_size;

    cudaFuncSetAttribute(we_gemm_tc, cudaFuncAttributeMaxDynamicSharedMemorySize, G1_SMEM);
    cudaFuncSetAttribute(attn_tc, cudaFuncAttributeMaxDynamicSharedMemorySize, SMEM_SZ);

    we_gemm_tc<<<dim3(HW2 / 128, MP / 128), 256, G1_SMEM>>>(word_emb, W_fc, b_fc); // (8, 20)
    transpose_we<<<dim3(HW2 / 64, BB), 256>>>();                                   // (16, 32)
    attn_tc<<<dim3(CC / 128, BB), 256, SMEM_SZ>>>(feat, out);                      // (4, 32)
}

// round 10
// speedup vs baseline: 1.8396x; 1.1358x over previous
#include <cuda_runtime.h>
#include <cuda_bf16.h>
#include <cstdint>

#define BB   32
#define CC   512
#define HW2  1024
#define NW   77
#define NP   80          // padded n
#define WD   256
#define MP   (BB * NP)   // 2560 padded rows

// ---------------- scratch (bf16 splits of we and we^T) ----------------
__device__ __nv_bfloat16 g_we_hi[(size_t)BB * NP * HW2];
__device__ __nv_bfloat16 g_we_lo[(size_t)BB * NP * HW2];
__device__ __nv_bfloat16 g_weT_hi[(size_t)BB * HW2 * NP];
__device__ __nv_bfloat16 g_weT_lo[(size_t)BB * HW2 * NP];

// ---------------- warp-MMA helpers ----------------
__device__ __forceinline__ uint32_t smem_to_u32(const void* p) {
    uint32_t a;
    asm("{ .reg .u64 t; cvta.to.shared.u64 t, %1; cvt.u32.u64 %0, t; }" : "=r"(a) : "l"(p));
    return a;
}
__device__ __forceinline__ void mma_bf16(float* c, const uint32_t* a, const uint32_t* b) {
    asm volatile(
        "mma.sync.aligned.m16n8k16.row.col.f32.bf16.bf16.f32 "
        "{%0,%1,%2,%3}, {%4,%5,%6,%7}, {%8,%9}, {%0,%1,%2,%3};"
        : "+f"(c[0]), "+f"(c[1]), "+f"(c[2]), "+f"(c[3])
        : "r"(a[0]), "r"(a[1]), "r"(a[2]), "r"(a[3]), "r"(b[0]), "r"(b[1]));
}
__device__ __forceinline__ void ldsm4(uint32_t* r, uint32_t addr) {
    asm volatile("ldmatrix.sync.aligned.m8n8.x4.shared.b16 {%0,%1,%2,%3}, [%4];"
        : "=r"(r[0]), "=r"(r[1]), "=r"(r[2]), "=r"(r[3]) : "r"(addr));
}
__device__ __forceinline__ void ldsm2(uint32_t* r, uint32_t addr) {
    asm volatile("ldmatrix.sync.aligned.m8n8.x2.shared.b16 {%0,%1}, [%2];"
        : "=r"(r[0]), "=r"(r[1]) : "r"(addr));
}
__device__ __forceinline__ void split2(float v0, float v1, uint32_t& ph, uint32_t& pl) {
    __nv_bfloat16 h0 = __float2bfloat16(v0), h1 = __float2bfloat16(v1);
    float r0 = v0 - __bfloat162float(h0), r1 = v1 - __bfloat162float(h1);
    __nv_bfloat16 l0 = __float2bfloat16(r0), l1 = __float2bfloat16(r1);
    ph = (uint32_t)__bfloat16_as_ushort(h0) | ((uint32_t)__bfloat16_as_ushort(h1) << 16);
    pl = (uint32_t)__bfloat16_as_ushort(l0) | ((uint32_t)__bfloat16_as_ushort(l1) << 16);
}

#define SA2 272   // 128-wide K slab: 136 bf16 row stride (128 data + 8 pad)
#define SW3 176   // phase-3 W row stride bytes (88 bf16)

// ---------------------------------------------------------------------------
// Kernel 1: we = word_emb @ W_fc^T + b_fc -> bf16 hi/lo splits.
// 512 threads, 16 warps = 8 rowgroups x 2 K-halves; K=128 slab resident;
// 2 outer iterations; smem reduction of the two K-half partials.
// ---------------------------------------------------------------------------
#define G1_AH 0
#define G1_AL 34816
#define G1_BH 69632
#define G1_BL 104448
#define G1_SMEM 139264
#define G1_RED_S 130   // fp32 reduction stride (floats)

__global__ __launch_bounds__(512, 1) void we_gemm_tc(const float* __restrict__ we_in,
                                                     const float* __restrict__ Wfc,
                                                     const float* __restrict__ bfc) {
    extern __shared__ char smem[];
    const uint32_t sb = smem_to_u32(smem);
    const int tid  = threadIdx.x;
    const int wid  = tid >> 5;
    const int lane = tid & 31;
    const int q    = lane & 3;
    const int g    = lane >> 2;
    const int rg   = wid & 7;
    const int kh   = wid >> 3;
    const int m0   = blockIdx.y * 128;
    const int k0   = blockIdx.x * 128;
    const int r0   = rg * 16;

    float acc[16][4];
#pragma unroll
    for (int t = 0; t < 16; t++)
#pragma unroll
        for (int j = 0; j < 4; j++) acc[t][j] = 0.f;

    const int am = lane >> 3;
    const int ar = lane & 7;
    const uint32_t aoff = (uint32_t)((r0 + (am & 1) * 8 + ar) * SA2 + (am >> 1) * 16);
    const uint32_t aaddr_h = sb + G1_AH + aoff;
    const uint32_t aaddr_l = sb + G1_AL + aoff;
    const uint32_t boff = (uint32_t)(ar * SA2 + ((lane >> 3) & 1) * 16);
    const uint32_t baddr_h = sb + G1_BH + boff;
    const uint32_t baddr_l = sb + G1_BL + boff;

    // loaders: 4 threads per row, 32 cols each
    const int lr = tid >> 2, lh = tid & 3;
    const int mp_l = m0 + lr;
    const int bb_l = mp_l / NP, nn_l = mp_l % NP;
    const bool a_valid = (nn_l < NW);
    const float* asrc = we_in + ((size_t)bb_l * NW + nn_l) * WD + lh * 32;
    const float* bsrc = Wfc + (size_t)(k0 + lr) * WD + lh * 32;

    for (int it = 0; it < 2; it++) {
        const int dc = it * 128;
        {
            char* ph_ = smem + G1_AH + lr * SA2 + lh * 64;
            char* pl_ = smem + G1_AL + lr * SA2 + lh * 64;
            char* qh_ = smem + G1_BH + lr * SA2 + lh * 64;
            char* ql_ = smem + G1_BL + lr * SA2 + lh * 64;
#pragma unroll
            for (int i = 0; i < 8; i++) {
                float4 v = a_valid ? *(const float4*)(asrc + dc + i * 4)
                                   : make_float4(0.f, 0.f, 0.f, 0.f);
                uint32_t p0h, p0l, p1h, p1l;
                split2(v.x, v.y, p0h, p0l);
                split2(v.z, v.w, p1h, p1l);
                *(uint32_t*)(ph_ + i * 8)     = p0h;
                *(uint32_t*)(ph_ + i * 8 + 4) = p1h;
                *(uint32_t*)(pl_ + i * 8)     = p0l;
                *(uint32_t*)(pl_ + i * 8 + 4) = p1l;
                float4 w = *(const float4*)(bsrc + dc + i * 4);
                split2(w.x, w.y, p0h, p0l);
                split2(w.z, w.w, p1h, p1l);
                *(uint32_t*)(qh_ + i * 8)     = p0h;
                *(uint32_t*)(qh_ + i * 8 + 4) = p1h;
                *(uint32_t*)(ql_ + i * 8)     = p0l;
                *(uint32_t*)(ql_ + i * 8 + 4) = p1l;
            }
        }
        __syncthreads();
#pragma unroll
        for (int ks = 0; ks < 4; ks++) {
            const uint32_t kb = (uint32_t)(kh * 128 + ks * 32);
            uint32_t a_h[4], a_l[4];
            ldsm4(a_h, aaddr_h + kb);
            ldsm4(a_l, aaddr_l + kb);
#pragma unroll
            for (int t = 0; t < 16; t++) {
                uint32_t bh[2], bl[2];
                ldsm2(bh, baddr_h + t * 8 * SA2 + kb);
                ldsm2(bl, baddr_l + t * 8 * SA2 + kb);
                mma_bf16(acc[t], a_h, bh);
                mma_bf16(acc[t], a_h, bl);
                mma_bf16(acc[t], a_l, bh);
            }
        }
        __syncthreads();
    }

    // reduce the two K-half partials via smem
    float* red = (float*)smem;   // 128 x 128 fp32, stride G1_RED_S
    if (kh == 1) {
#pragma unroll
        for (int t = 0; t < 16; t++) {
            const int col = t * 8 + 2 * q;
            red[(r0 + g) * G1_RED_S + col]     = acc[t][0];
            red[(r0 + g) * G1_RED_S + col + 1] = acc[t][1];
            red[(r0 + g + 8) * G1_RED_S + col]     = acc[t][2];
            red[(r0 + g + 8) * G1_RED_S + col + 1] = acc[t][3];
        }
    }
    __syncthreads();
    if (kh == 0) {
        const int mp0 = m0 + r0 + g;
        const int mp1 = mp0 + 8;
        const bool v0ok = ((mp0 % NP) < NW);
        const bool v1ok = ((mp1 % NP) < NW);
#pragma unroll
        for (int t = 0; t < 16; t++) {
            const int col = k0 + t * 8 + 2 * q;
            const int lc  = t * 8 + 2 * q;
            const float b0 = bfc[col], b1 = bfc[col + 1];
            float v00 = v0ok ? acc[t][0] + red[(r0 + g) * G1_RED_S + lc]     + b0 : 0.f;
            float v01 = v0ok ? acc[t][1] + red[(r0 + g) * G1_RED_S + lc + 1] + b1 : 0.f;
            float v10 = v1ok ? acc[t][2] + red[(r0 + g + 8) * G1_RED_S + lc]     + b0 : 0.f;
            float v11 = v1ok ? acc[t][3] + red[(r0 + g + 8) * G1_RED_S + lc + 1] + b1 : 0.f;
            uint32_t ph, pl;
            split2(v00, v01, ph, pl);
            *(uint32_t*)(g_we_hi + (size_t)mp0 * HW2 + col) = ph;
            *(uint32_t*)(g_we_lo + (size_t)mp0 * HW2 + col) = pl;
            split2(v10, v11, ph, pl);
            *(uint32_t*)(g_we_hi + (size_t)mp1 * HW2 + col) = ph;
            *(uint32_t*)(g_we_lo + (size_t)mp1 * HW2 + col) = pl;
        }
    }
}

// ---------------------------------------------------------------------------
// Kernel 2: transpose splits -> weT[b][k][n]
// ---------------------------------------------------------------------------
__global__ void transpose_we() {
    __shared__ unsigned short sh[NP][66];
    __shared__ unsigned short sl[NP][66];
    const int tid = threadIdx.x;
    const int k0  = blockIdx.x * 64;
    const int b   = blockIdx.y;

    for (int i = tid; i < NP * 32; i += 256) {
        int n = i >> 5, w = i & 31;
        uint32_t vh = *(const uint32_t*)(g_we_hi + ((size_t)b * NP + n) * HW2 + k0 + 2 * w);
        uint32_t vl = *(const uint32_t*)(g_we_lo + ((size_t)b * NP + n) * HW2 + k0 + 2 * w);
        sh[n][2 * w] = (unsigned short)(vh & 0xffff); sh[n][2 * w + 1] = (unsigned short)(vh >> 16);
        sl[n][2 * w] = (unsigned short)(vl & 0xffff); sl[n][2 * w + 1] = (unsigned short)(vl >> 16);
    }
    __syncthreads();
    for (int i = tid; i < 64 * 40; i += 256) {
        int k = i / 40, j = i % 40;
        uint32_t oh = (uint32_t)sh[2 * j][k] | ((uint32_t)sh[2 * j + 1][k] << 16);
        uint32_t ol = (uint32_t)sl[2 * j][k] | ((uint32_t)sl[2 * j + 1][k] << 16);
        size_t off = ((size_t)b * HW2 + k0 + k) * NP;
        *(uint32_t*)(g_weT_hi + off + 2 * j) = oh;
        *(uint32_t*)(g_weT_lo + off + 2 * j) = ol;
    }
}

// ---------------------------------------------------------------------------
// Kernel 3: fused attention, 512 threads = 16 warps.
// Phase 1: K-split (8 rowgroups x 2 K-halves), K=128 slab resident, 8 iters.
// Phase 2: smem-reduce partials, register softmax, att fragments -> smem.
// Phase 3: 16 warps = 8 rowgroups x 2 col-halves over 8 output chunks.
// ---------------------------------------------------------------------------
#define AH2 0
#define AL2 34816
#define BH2 69632
#define BL2 91392
#define SMEM_ATT 113152
// phase-2/3 overlays
#define ATTH_W 0          // uint32 words, 128 x 41
#define ATTL_W 20992
#define RED3   43008      // fp32, 128 x 81
#define WH3    43008      // bytes (after RED consumed)
#define WL3    65536
#define ATT_S  41
#define RED3_S 81

__global__ __launch_bounds__(512, 1) void attn_tc(const float* __restrict__ feat,
                                                  float* __restrict__ out) {
    extern __shared__ char smem[];
    const uint32_t sb = smem_to_u32(smem);
    const int tid  = threadIdx.x;
    const int wid  = tid >> 5;
    const int lane = tid & 31;
    const int q    = lane & 3;
    const int g    = lane >> 2;
    const int rg   = wid & 7;
    const int kh   = wid >> 3;
    const int b    = blockIdx.y;
    const int c0   = blockIdx.x * 128;
    const int r0   = rg * 16;

    const float* fb = feat + ((size_t)b * CC + c0) * HW2;
    const __nv_bfloat16* weh = g_we_hi + (size_t)b * NP * HW2;
    const __nv_bfloat16* wel = g_we_lo + (size_t)b * NP * HW2;

    // ================= Phase 1: scores = f . we^T =================
    float acc[10][4];
#pragma unroll
    for (int t = 0; t < 10; t++)
#pragma unroll
        for (int j = 0; j < 4; j++) acc[t][j] = 0.f;

    const int am = lane >> 3;
    const int ar = lane & 7;
    const uint32_t aoff = (uint32_t)((r0 + (am & 1) * 8 + ar) * SA2 + (am >> 1) * 16);
    const uint32_t aaddr_h = sb + AH2 + aoff;
    const uint32_t aaddr_l = sb + AL2 + aoff;
    const uint32_t boff = (uint32_t)(ar * SA2 + ((lane >> 3) & 1) * 16);
    const uint32_t baddr_h = sb + BH2 + boff;
    const uint32_t baddr_l = sb + BL2 + boff;

    const int lr = tid >> 2, lh = tid & 3;

    for (int it = 0; it < 8; it++) {
        const int kc = it * 128;
        // A tile: 128 rows x 128 cols fp32 -> hi/lo splits
        {
            const float* src = fb + (size_t)lr * HW2 + kc + lh * 32;
            char* ph_ = smem + AH2 + lr * SA2 + lh * 64;
            char* pl_ = smem + AL2 + lr * SA2 + lh * 64;
#pragma unroll
            for (int i = 0; i < 8; i++) {
                float4 v = *(const float4*)(src + i * 4);
                uint32_t p0h, p0l, p1h, p1l;
                split2(v.x, v.y, p0h, p0l);
                split2(v.z, v.w, p1h, p1l);
                *(uint32_t*)(ph_ + i * 8)     = p0h;
                *(uint32_t*)(ph_ + i * 8 + 4) = p1h;
                *(uint32_t*)(pl_ + i * 8)     = p0l;
                *(uint32_t*)(pl_ + i * 8 + 4) = p1l;
            }
        }
        // B tile: 80 rows x 128 cols bf16 hi/lo (pure copy)
        for (int i = tid; i < NP * 64; i += 512) {
            int n = i >> 6, w = i & 63;
            *(uint32_t*)(smem + BH2 + n * SA2 + w * 4) =
                *(const uint32_t*)(weh + (size_t)n * HW2 + kc + 2 * w);
            *(uint32_t*)(smem + BL2 + n * SA2 + w * 4) =
                *(const uint32_t*)(wel + (size_t)n * HW2 + kc + 2 * w);
        }
        __syncthreads();
#pragma unroll
        for (int ks = 0; ks < 4; ks++) {
            const uint32_t kb = (uint32_t)(kh * 128 + ks * 32);
            uint32_t a_h[4], a_l[4];
            ldsm4(a_h, aaddr_h + kb);
            ldsm4(a_l, aaddr_l + kb);
#pragma unroll
            for (int t = 0; t < 10; t++) {
                uint32_t bh[2], bl[2];
                ldsm2(bh, baddr_h + t * 8 * SA2 + kb);
                ldsm2(bl, baddr_l + t * 8 * SA2 + kb);
                mma_bf16(acc[t], a_h, bh);
                mma_bf16(acc[t], a_h, bl);
                mma_bf16(acc[t], a_l, bh);
            }
        }
        __syncthreads();
    }

    // ================= Phase 2: reduce + softmax + att frags =================
    float* red = (float*)(smem + RED3);
    if (kh == 1) {
#pragma unroll
        for (int t = 0; t < 10; t++) {
            const int col = t * 8 + 2 * q;
            red[(r0 + g) * RED3_S + col]     = acc[t][0];
            red[(r0 + g) * RED3_S + col + 1] = acc[t][1];
            red[(r0 + g + 8) * RED3_S + col]     = acc[t][2];
            red[(r0 + g + 8) * RED3_S + col + 1] = acc[t][3];
        }
    }
    __syncthreads();
    uint32_t* atth = (uint32_t*)(smem + ATTH_W);
    uint32_t* attl = (uint32_t*)(smem + ATTL_W);
    if (kh == 0) {
#pragma unroll
        for (int t = 0; t < 10; t++) {
            const int col = t * 8 + 2 * q;
            acc[t][0] += red[(r0 + g) * RED3_S + col];
            acc[t][1] += red[(r0 + g) * RED3_S + col + 1];
            acc[t][2] += red[(r0 + g + 8) * RED3_S + col];
            acc[t][3] += red[(r0 + g + 8) * RED3_S + col + 1];
        }
        float mx0 = -1e30f, mx1 = -1e30f;
#pragma unroll
        for (int t = 0; t < 10; t++) {
            int col = t * 8 + 2 * q;
            if (col < NW)     { mx0 = fmaxf(mx0, acc[t][0]); mx1 = fmaxf(mx1, acc[t][2]); }
            if (col + 1 < NW) { mx0 = fmaxf(mx0, acc[t][1]); mx1 = fmaxf(mx1, acc[t][3]); }
        }
        mx0 = fmaxf(mx0, __shfl_xor_sync(0xffffffffu, mx0, 1));
        mx0 = fmaxf(mx0, __shfl_xor_sync(0xffffffffu, mx0, 2));
        mx1 = fmaxf(mx1, __shfl_xor_sync(0xffffffffu, mx1, 1));
        mx1 = fmaxf(mx1, __shfl_xor_sync(0xffffffffu, mx1, 2));
        float s0 = 0.f, s1 = 0.f;
#pragma unroll
        for (int t = 0; t < 10; t++) {
            int col = t * 8 + 2 * q;
            float e0 = (col < NW)     ? __expf(acc[t][0] - mx0) : 0.f;
            float e1 = (col + 1 < NW) ? __expf(acc[t][1] - mx0) : 0.f;
            float e2 = (col < NW)     ? __expf(acc[t][2] - mx1) : 0.f;
            float e3 = (col + 1 < NW) ? __expf(acc[t][3] - mx1) : 0.f;
            acc[t][0] = e0; acc[t][1] = e1; acc[t][2] = e2; acc[t][3] = e3;
            s0 += e0 + e1; s1 += e2 + e3;
        }
        s0 += __shfl_xor_sync(0xffffffffu, s0, 1);
        s0 += __shfl_xor_sync(0xffffffffu, s0, 2);
        s1 += __shfl_xor_sync(0xffffffffu, s1, 1);
        s1 += __shfl_xor_sync(0xffffffffu, s1, 2);
        const float inv0 = 1.f / s0, inv1 = 1.f / s1;
#pragma unroll
        for (int t = 0; t < 10; t++) {
            const int p = t * 4 + q;    // column pair index
            uint32_t ph, pl;
            split2(acc[t][0] * inv0, acc[t][1] * inv0, ph, pl);
            atth[(r0 + g) * ATT_S + p] = ph;
            attl[(r0 + g) * ATT_S + p] = pl;
            split2(acc[t][2] * inv1, acc[t][3] * inv1, ph, pl);
            atth[(r0 + g + 8) * ATT_S + p] = ph;
            attl[(r0 + g + 8) * ATT_S + p] = pl;
        }
    }
    __syncthreads();

    // ================= Phase 3: out = att @ weT =================
    const int ch2 = kh;   // col-half of the 128-col chunk
    const uint32_t wboff = (uint32_t)((lane & 7) * SW3 + ((lane >> 3) & 1) * 16);
    const uint32_t wh_base = sb + WH3 + wboff + (uint32_t)(ch2 * 8) * 8 * SW3;
    const uint32_t wl_base = sb + WL3 + wboff + (uint32_t)(ch2 * 8) * 8 * SW3;

    for (int oc = 0; oc < 8; oc++) {
        const int k0 = oc * 128;
        const __nv_bfloat16* th = g_weT_hi + ((size_t)b * HW2 + k0) * NP;
        const __nv_bfloat16* tl = g_weT_lo + ((size_t)b * HW2 + k0) * NP;
        for (int i = tid; i < 128 * 40; i += 512) {
            int r = i / 40, w = i % 40;
            *(uint32_t*)(smem + WH3 + r * SW3 + w * 4) =
                *(const uint32_t*)(th + (size_t)r * NP + 2 * w);
            *(uint32_t*)(smem + WL3 + r * SW3 + w * 4) =
                *(const uint32_t*)(tl + (size_t)r * NP + 2 * w);
        }
        __syncthreads();

        float acc2[8][4];
#pragma unroll
        for (int t = 0; t < 8; t++)
#pragma unroll
            for (int j = 0; j < 4; j++) acc2[t][j] = 0.f;

#pragma unroll
        for (int ks = 0; ks < 5; ks++) {
            uint32_t a_h[4], a_l[4];
            const int p0 = ks * 8 + q;
            a_h[0] = atth[(r0 + g) * ATT_S + p0];
            a_h[1] = atth[(r0 + g + 8) * ATT_S + p0];
            a_h[2] = atth[(r0 + g) * ATT_S + p0 + 4];
            a_h[3] = atth[(r0 + g + 8) * ATT_S + p0 + 4];
            a_l[0] = attl[(r0 + g) * ATT_S + p0];
            a_l[1] = attl[(r0 + g + 8) * ATT_S + p0];
            a_l[2] = attl[(r0 + g) * ATT_S + p0 + 4];
            a_l[3] = attl[(r0 + g + 8) * ATT_S + p0 + 4];
#pragma unroll
            for (int kt = 0; kt < 8; kt++) {
                uint32_t bh[2], bl[2];
                ldsm2(bh, wh_base + kt * 8 * SW3 + ks * 32);
                ldsm2(bl, wl_base + kt * 8 * SW3 + ks * 32);
                mma_bf16(acc2[kt], a_h, bh);
                mma_bf16(acc2[kt], a_h, bl);
                mma_bf16(acc2[kt], a_l, bh);
            }
        }

        float* ob = out + ((size_t)b * CC + c0 + r0) * HW2 + k0 + ch2 * 64;
#pragma unroll
        for (int kt = 0; kt < 8; kt++) {
            int col = kt * 8 + 2 * q;
            *(float2*)&ob[(size_t)g * HW2 + col]       = make_float2(acc2[kt][0], acc2[kt][1]);
            *(float2*)&ob[(size_t)(g + 8) * HW2 + col] = make_float2(acc2[kt][2], acc2[kt][3]);
        }
        __syncthreads();
    }
}

// ---------------------------------------------------------------------------
extern "C" void kernel_launch(void* const* d_in, const int* in_sizes, int n_in,
                              void* d_out, int out_size) {
    const float* feat     = (const float*)d_in[0];
    const float* word_emb = (const float*)d_in[1];
    const float* W_fc     = (const float*)d_in[2];
    const float* b_fc     = (const float*)d_in[3];
    float* out            = (float*)d_out;
    (void)in_sizes; (void)n_in; (void)out_size;

    cudaFuncSetAttribute(we_gemm_tc, cudaFuncAttributeMaxDynamicSharedMemorySize, G1_SMEM);
    cudaFuncSetAttribute(attn_tc, cudaFuncAttributeMaxDynamicSharedMemorySize, SMEM_ATT);

    we_gemm_tc<<<dim3(HW2 / 128, MP / 128), 512, G1_SMEM>>>(word_emb, W_fc, b_fc); // (8, 20)
    transpose_we<<<dim3(HW2 / 64, BB), 256>>>();                                   // (16, 32)
    attn_tc<<<dim3(CC / 128, BB), 512, SMEM_ATT>>>(feat, out);                     // (4, 32)
}

// round 11
// speedup vs baseline: 2.4608x; 1.3377x over previous
#include <cuda_runtime.h>
#include <cuda_bf16.h>
#include <cstdint>

#define BB   32
#define CC   512
#define HW2  1024
#define NW   77
#define NP   80          // padded n
#define WD   256
#define MP   (BB * NP)   // 2560 padded rows

// ---------------- scratch ----------------
__device__ __nv_bfloat16 g_a_hi[(size_t)MP * WD];       // word_emb splits (padded rows)
__device__ __nv_bfloat16 g_a_lo[(size_t)MP * WD];
__device__ __nv_bfloat16 g_w_hi[(size_t)HW2 * WD];      // W_fc splits
__device__ __nv_bfloat16 g_w_lo[(size_t)HW2 * WD];
__device__ __nv_bfloat16 g_we_hi[(size_t)BB * NP * HW2];
__device__ __nv_bfloat16 g_we_lo[(size_t)BB * NP * HW2];
__device__ __nv_bfloat16 g_weT_hi[(size_t)BB * HW2 * NP];
__device__ __nv_bfloat16 g_weT_lo[(size_t)BB * HW2 * NP];

// ---------------- helpers ----------------
__device__ __forceinline__ uint32_t smem_to_u32(const void* p) {
    uint32_t a;
    asm("{ .reg .u64 t; cvta.to.shared.u64 t, %1; cvt.u32.u64 %0, t; }" : "=r"(a) : "l"(p));
    return a;
}
__device__ __forceinline__ void mma_bf16(float* c, const uint32_t* a, uint32_t b0, uint32_t b1) {
    asm volatile(
        "mma.sync.aligned.m16n8k16.row.col.f32.bf16.bf16.f32 "
        "{%0,%1,%2,%3}, {%4,%5,%6,%7}, {%8,%9}, {%0,%1,%2,%3};"
        : "+f"(c[0]), "+f"(c[1]), "+f"(c[2]), "+f"(c[3])
        : "r"(a[0]), "r"(a[1]), "r"(a[2]), "r"(a[3]), "r"(b0), "r"(b1));
}
__device__ __forceinline__ void ldsm4(uint32_t* r, uint32_t addr) {
    asm volatile("ldmatrix.sync.aligned.m8n8.x4.shared.b16 {%0,%1,%2,%3}, [%4];"
        : "=r"(r[0]), "=r"(r[1]), "=r"(r[2]), "=r"(r[3]) : "r"(addr));
}
__device__ __forceinline__ void ldsm2(uint32_t* r, uint32_t addr) {
    asm volatile("ldmatrix.sync.aligned.m8n8.x2.shared.b16 {%0,%1}, [%2];"
        : "=r"(r[0]), "=r"(r[1]) : "r"(addr));
}
__device__ __forceinline__ void split2(float v0, float v1, uint32_t& ph, uint32_t& pl) {
    __nv_bfloat16 h0 = __float2bfloat16(v0), h1 = __float2bfloat16(v1);
    float r0 = v0 - __bfloat162float(h0), r1 = v1 - __bfloat162float(h1);
    __nv_bfloat16 l0 = __float2bfloat16(r0), l1 = __float2bfloat16(r1);
    ph = (uint32_t)__bfloat16_as_ushort(h0) | ((uint32_t)__bfloat16_as_ushort(h1) << 16);
    pl = (uint32_t)__bfloat16_as_ushort(l0) | ((uint32_t)__bfloat16_as_ushort(l1) << 16);
}
#define CP16(dst, src) asm volatile("cp.async.cg.shared.global [%0], [%1], 16;" :: "r"(dst), "l"(src))
#define CP_COMMIT()    asm volatile("cp.async.commit_group;" ::: "memory")
#define CP_WAIT0()     asm volatile("cp.async.wait_group 0;" ::: "memory")
#define CP_WAIT1()     asm volatile("cp.async.wait_group 1;" ::: "memory")

#define SA  144   // 64-wide bf16 tile row stride bytes (72 bf16)
#define SW3 176   // phase-3 W row stride bytes (88 bf16)

// ---------------------------------------------------------------------------
// Kernel 0: elementwise bf16 hi/lo split of word_emb (padded to NP rows) + W_fc
// ---------------------------------------------------------------------------
#define A_TASKS (MP * WD / 4)     // 163840
#define W_TASKS (HW2 * WD / 4)    // 65536
__global__ void split_inputs(const float* __restrict__ we_in,
                             const float* __restrict__ Wfc) {
    int idx = blockIdx.x * 256 + threadIdx.x;
    if (idx < A_TASKS) {
        int mp = idx >> 6, c4 = idx & 63;
        int bb = mp / NP, nn = mp % NP;
        float4 v = make_float4(0.f, 0.f, 0.f, 0.f);
        if (nn < NW) v = *(const float4*)(we_in + ((size_t)bb * NW + nn) * WD + c4 * 4);
        uint32_t h0, l0, h1, l1;
        split2(v.x, v.y, h0, l0);
        split2(v.z, v.w, h1, l1);
        *(uint2*)(g_a_hi + (size_t)mp * WD + c4 * 4) = make_uint2(h0, h1);
        *(uint2*)(g_a_lo + (size_t)mp * WD + c4 * 4) = make_uint2(l0, l1);
    } else if (idx < A_TASKS + W_TASKS) {
        int j = idx - A_TASKS;
        int r = j >> 6, c4 = j & 63;
        float4 v = *(const float4*)(Wfc + (size_t)r * WD + c4 * 4);
        uint32_t h0, l0, h1, l1;
        split2(v.x, v.y, h0, l0);
        split2(v.z, v.w, h1, l1);
        *(uint2*)(g_w_hi + (size_t)r * WD + c4 * 4) = make_uint2(h0, h1);
        *(uint2*)(g_w_lo + (size_t)r * WD + c4 * 4) = make_uint2(l0, l1);
    }
}

// ---------------------------------------------------------------------------
// Kernel 1: we = word_emb @ W_fc^T + b_fc (pure bf16 GEMM, cp.async 2-stage)
// 256 threads, 8 warps = 4 rowgroups x 2 colgroups; warp tile 32 x 64.
// K = 256 in 4 chunks of 64, double-buffered.
// ---------------------------------------------------------------------------
#define G_AH 0
#define G_AL 18432
#define G_BH 36864
#define G_BL 55296
#define G_STAGE 73728
#define G_SMEM  147456

__global__ __launch_bounds__(256, 1) void we_gemm_tc(const float* __restrict__ bfc) {
    extern __shared__ char smem[];
    const uint32_t sb = smem_to_u32(smem);
    const int tid  = threadIdx.x;
    const int wid  = tid >> 5;
    const int lane = tid & 31;
    const int q    = lane & 3;
    const int g    = lane >> 2;
    const int rg   = wid & 3;
    const int cg   = wid >> 2;
    const int m0   = blockIdx.y * 128;
    const int k0   = blockIdx.x * 128;
    const int r0   = rg * 32;
    const int c0w  = cg * 64;

    float acc[2][8][4];
#pragma unroll
    for (int mt = 0; mt < 2; mt++)
#pragma unroll
        for (int t = 0; t < 8; t++)
#pragma unroll
            for (int j = 0; j < 4; j++) acc[mt][t][j] = 0.f;

    const int am = lane >> 3;
    const int ar = lane & 7;
    const uint32_t arow = (uint32_t)((am & 1) * 8 + ar) * SA + (uint32_t)(am >> 1) * 16;
    const uint32_t b4row = (uint32_t)((lane >> 4) * 8 + ar) * SA + (uint32_t)((lane >> 3) & 1) * 16;

    // cp.async loader for chunk ch into stage s
    auto load_chunk = [&](int ch, int s) {
        const int kc = ch * 64;
        const uint32_t st = sb + (uint32_t)s * G_STAGE;
#pragma unroll
        for (int i = tid; i < 1024; i += 256) {
            int r = i >> 3, cchunk = i & 7;
            uint32_t off = (uint32_t)r * SA + (uint32_t)cchunk * 16;
            const __nv_bfloat16* sa = g_a_hi + (size_t)(m0 + r) * WD + kc + cchunk * 8;
            const __nv_bfloat16* sal = g_a_lo + (size_t)(m0 + r) * WD + kc + cchunk * 8;
            const __nv_bfloat16* sw = g_w_hi + (size_t)(k0 + r) * WD + kc + cchunk * 8;
            const __nv_bfloat16* swl = g_w_lo + (size_t)(k0 + r) * WD + kc + cchunk * 8;
            CP16(st + G_AH + off, sa);
            CP16(st + G_AL + off, sal);
            CP16(st + G_BH + off, sw);
            CP16(st + G_BL + off, swl);
        }
    };

    load_chunk(0, 0);
    CP_COMMIT();

    for (int ch = 0; ch < 4; ch++) {
        const int s = ch & 1;
        if (ch < 3) { load_chunk(ch + 1, s ^ 1); CP_COMMIT(); }
        if (ch < 3) CP_WAIT1(); else CP_WAIT0();
        __syncthreads();

        const uint32_t st = sb + (uint32_t)s * G_STAGE;
#pragma unroll
        for (int ks = 0; ks < 4; ks++) {
            const uint32_t kb = (uint32_t)ks * 32;
            uint32_t a_h[2][4], a_l[2][4];
#pragma unroll
            for (int mt = 0; mt < 2; mt++) {
                uint32_t ao = (uint32_t)(r0 + mt * 16) * SA + arow + kb;
                ldsm4(a_h[mt], st + G_AH + ao);
                ldsm4(a_l[mt], st + G_AL + ao);
            }
            uint32_t b_h[4][4], b_l[4][4];
#pragma unroll
            for (int tp = 0; tp < 4; tp++) {
                uint32_t bo = (uint32_t)(c0w + tp * 16) * SA + b4row + kb;
                ldsm4(b_h[tp], st + G_BH + bo);
                ldsm4(b_l[tp], st + G_BL + bo);
            }
#pragma unroll
            for (int mt = 0; mt < 2; mt++)
#pragma unroll
                for (int tp = 0; tp < 4; tp++) {
                    mma_bf16(acc[mt][2 * tp],     a_h[mt], b_h[tp][0], b_h[tp][1]);
                    mma_bf16(acc[mt][2 * tp],     a_h[mt], b_l[tp][0], b_l[tp][1]);
                    mma_bf16(acc[mt][2 * tp],     a_l[mt], b_h[tp][0], b_h[tp][1]);
                    mma_bf16(acc[mt][2 * tp + 1], a_h[mt], b_h[tp][2], b_h[tp][3]);
                    mma_bf16(acc[mt][2 * tp + 1], a_h[mt], b_l[tp][2], b_l[tp][3]);
                    mma_bf16(acc[mt][2 * tp + 1], a_l[mt], b_h[tp][2], b_h[tp][3]);
                }
        }
        __syncthreads();
    }

    // epilogue
#pragma unroll
    for (int mt = 0; mt < 2; mt++) {
        const int mp0 = m0 + r0 + mt * 16 + g;
        const int mp1 = mp0 + 8;
        const bool v0ok = ((mp0 % NP) < NW);
        const bool v1ok = ((mp1 % NP) < NW);
#pragma unroll
        for (int t = 0; t < 8; t++) {
            const int col = k0 + c0w + t * 8 + 2 * q;
            const float b0 = bfc[col], b1 = bfc[col + 1];
            float v00 = v0ok ? acc[mt][t][0] + b0 : 0.f;
            float v01 = v0ok ? acc[mt][t][1] + b1 : 0.f;
            float v10 = v1ok ? acc[mt][t][2] + b0 : 0.f;
            float v11 = v1ok ? acc[mt][t][3] + b1 : 0.f;
            uint32_t ph, pl;
            split2(v00, v01, ph, pl);
            *(uint32_t*)(g_we_hi + (size_t)mp0 * HW2 + col) = ph;
            *(uint32_t*)(g_we_lo + (size_t)mp0 * HW2 + col) = pl;
            split2(v10, v11, ph, pl);
            *(uint32_t*)(g_we_hi + (size_t)mp1 * HW2 + col) = ph;
            *(uint32_t*)(g_we_lo + (size_t)mp1 * HW2 + col) = pl;
        }
    }
}

// ---------------------------------------------------------------------------
// Kernel 2: transpose splits -> weT[b][k][n]
// ---------------------------------------------------------------------------
__global__ void transpose_we() {
    __shared__ unsigned short sh[NP][66];
    __shared__ unsigned short sl[NP][66];
    const int tid = threadIdx.x;
    const int k0  = blockIdx.x * 64;
    const int b   = blockIdx.y;

    for (int i = tid; i < NP * 32; i += 256) {
        int n = i >> 5, w = i & 31;
        uint32_t vh = *(const uint32_t*)(g_we_hi + ((size_t)b * NP + n) * HW2 + k0 + 2 * w);
        uint32_t vl = *(const uint32_t*)(g_we_lo + ((size_t)b * NP + n) * HW2 + k0 + 2 * w);
        sh[n][2 * w] = (unsigned short)(vh & 0xffff); sh[n][2 * w + 1] = (unsigned short)(vh >> 16);
        sl[n][2 * w] = (unsigned short)(vl & 0xffff); sl[n][2 * w + 1] = (unsigned short)(vl >> 16);
    }
    __syncthreads();
    for (int i = tid; i < 64 * 40; i += 256) {
        int k = i / 40, j = i % 40;
        uint32_t oh = (uint32_t)sh[2 * j][k] | ((uint32_t)sh[2 * j + 1][k] << 16);
        uint32_t ol = (uint32_t)sl[2 * j][k] | ((uint32_t)sl[2 * j + 1][k] << 16);
        size_t off = ((size_t)b * HW2 + k0 + k) * NP;
        *(uint32_t*)(g_weT_hi + off + 2 * j) = oh;
        *(uint32_t*)(g_weT_lo + off + 2 * j) = ol;
    }
}

// ---------------------------------------------------------------------------
// Kernel 3: fused attention. 256 threads, 8 warps = 4 rowgroups x 2 colgroups.
// Phase 1: scores via 2-stage pipeline (A: LDG prefetch + convert; B: cp.async)
// Phase 2: softmax from smem scores (W tile 0 prefetched concurrently)
// Phase 3: out = att @ weT, cp.async double-buffered W tiles.
// ---------------------------------------------------------------------------
// phase-1 stages (2 x 59904)
#define P1_AH 0
#define P1_AL 18432
#define P1_BH 36864
#define P1_BL 48384
#define P1_STAGE 59904
// overlays
#define ATTH_OFF 0          // uint32 [128][41]
#define ATTL_OFF 20992
#define SCR_OFF  41984      // fp32 [128][81]
#define WS1_OFF  41984      // W stage 1 (reuses score region after softmax)
#define WS0_OFF  87040      // W stage 0
#define W_HL     22528      // lo offset inside W stage
#define ATT_S    41
#define SCR_S    81
#define SMEM_ATT 132096

__global__ __launch_bounds__(256, 1) void attn_tc(const float* __restrict__ feat,
                                                  float* __restrict__ out) {
    extern __shared__ char smem[];
    const uint32_t sb = smem_to_u32(smem);
    const int tid  = threadIdx.x;
    const int wid  = tid >> 5;
    const int lane = tid & 31;
    const int q    = lane & 3;
    const int g    = lane >> 2;
    const int rg   = wid & 3;
    const int cg   = wid >> 2;
    const int b    = blockIdx.y;
    const int c0   = blockIdx.x * 128;
    const int r0   = rg * 32;

    const float* fb = feat + ((size_t)b * CC + c0) * HW2;
    const __nv_bfloat16* weh = g_we_hi + (size_t)b * NP * HW2;
    const __nv_bfloat16* wel = g_we_lo + (size_t)b * NP * HW2;

    const int am = lane >> 3;
    const int ar = lane & 7;
    const uint32_t arow = (uint32_t)((am & 1) * 8 + ar) * SA + (uint32_t)(am >> 1) * 16;
    const uint32_t b4row = (uint32_t)((lane >> 4) * 8 + ar) * SA + (uint32_t)((lane >> 3) & 1) * 16;
    const uint32_t b2row = (uint32_t)ar * SA + (uint32_t)((lane >> 3) & 1) * 16;

    // ---- phase-1 loaders ----
    const int lr = tid >> 1, lh = tid & 1;   // A: 2 threads/row, 32 cols each
    auto load_A_regs = [&](int ch, float4* pf) {
        const float* src = fb + (size_t)lr * HW2 + ch * 64 + lh * 32;
#pragma unroll
        for (int i = 0; i < 8; i++) pf[i] = *(const float4*)(src + i * 4);
    };
    auto store_A = [&](int s, const float4* pf) {
        char* ph_ = smem + s * P1_STAGE + P1_AH + lr * SA + lh * 64;
        char* pl_ = smem + s * P1_STAGE + P1_AL + lr * SA + lh * 64;
#pragma unroll
        for (int i = 0; i < 8; i++) {
            uint32_t p0h, p0l, p1h, p1l;
            split2(pf[i].x, pf[i].y, p0h, p0l);
            split2(pf[i].z, pf[i].w, p1h, p1l);
            *(uint32_t*)(ph_ + i * 8)     = p0h;
            *(uint32_t*)(ph_ + i * 8 + 4) = p1h;
            *(uint32_t*)(pl_ + i * 8)     = p0l;
            *(uint32_t*)(pl_ + i * 8 + 4) = p1l;
        }
    };
    auto load_B = [&](int ch, int s) {
        const int kc = ch * 64;
        const uint32_t st = sb + (uint32_t)s * P1_STAGE;
        for (int i = tid; i < 640; i += 256) {
            int r = i >> 3, cch = i & 7;
            uint32_t off = (uint32_t)r * SA + (uint32_t)cch * 16;
            CP16(st + P1_BH + off, weh + (size_t)r * HW2 + kc + cch * 8);
            CP16(st + P1_BL + off, wel + (size_t)r * HW2 + kc + cch * 8);
        }
    };

    // ================= Phase 1 =================
    float acc[2][5][4];
#pragma unroll
    for (int mt = 0; mt < 2; mt++)
#pragma unroll
        for (int t = 0; t < 5; t++)
#pragma unroll
            for (int j = 0; j < 4; j++) acc[mt][t][j] = 0.f;

    const int c0w = cg * 40;

    float4 pf[8];
    load_A_regs(0, pf);
    load_B(0, 0);
    CP_COMMIT();
    store_A(0, pf);

    for (int it = 0; it < 16; it++) {
        const int s = it & 1;
        if (it < 15) {
            load_A_regs(it + 1, pf);
            load_B(it + 1, s ^ 1);
            CP_COMMIT();
        }
        if (it < 15) CP_WAIT1(); else CP_WAIT0();
        __syncthreads();

        const uint32_t st = sb + (uint32_t)s * P1_STAGE;
#pragma unroll
        for (int ks = 0; ks < 4; ks++) {
            const uint32_t kb = (uint32_t)ks * 32;
            uint32_t a_h[2][4], a_l[2][4];
#pragma unroll
            for (int mt = 0; mt < 2; mt++) {
                uint32_t ao = (uint32_t)(r0 + mt * 16) * SA + arow + kb;
                ldsm4(a_h[mt], st + P1_AH + ao);
                ldsm4(a_l[mt], st + P1_AL + ao);
            }
            uint32_t b_h[2][4], b_l[2][4], b2h[2], b2l[2];
#pragma unroll
            for (int tp = 0; tp < 2; tp++) {
                uint32_t bo = (uint32_t)(c0w + tp * 16) * SA + b4row + kb;
                ldsm4(b_h[tp], st + P1_BH + bo);
                ldsm4(b_l[tp], st + P1_BL + bo);
            }
            {
                uint32_t bo = (uint32_t)(c0w + 32) * SA + b2row + kb;
                ldsm2(b2h, st + P1_BH + bo);
                ldsm2(b2l, st + P1_BL + bo);
            }
#pragma unroll
            for (int mt = 0; mt < 2; mt++) {
#pragma unroll
                for (int tp = 0; tp < 2; tp++) {
                    mma_bf16(acc[mt][2 * tp],     a_h[mt], b_h[tp][0], b_h[tp][1]);
                    mma_bf16(acc[mt][2 * tp],     a_h[mt], b_l[tp][0], b_l[tp][1]);
                    mma_bf16(acc[mt][2 * tp],     a_l[mt], b_h[tp][0], b_h[tp][1]);
                    mma_bf16(acc[mt][2 * tp + 1], a_h[mt], b_h[tp][2], b_h[tp][3]);
                    mma_bf16(acc[mt][2 * tp + 1], a_h[mt], b_l[tp][2], b_l[tp][3]);
                    mma_bf16(acc[mt][2 * tp + 1], a_l[mt], b_h[tp][2], b_h[tp][3]);
                }
                mma_bf16(acc[mt][4], a_h[mt], b2h[0], b2h[1]);
                mma_bf16(acc[mt][4], a_h[mt], b2l[0], b2l[1]);
                mma_bf16(acc[mt][4], a_l[mt], b2h[0], b2h[1]);
            }
        }
        if (it < 15) store_A(s ^ 1, pf);
        __syncthreads();
    }

    // ---- write scores to smem ----
    float* scr = (float*)(smem + SCR_OFF);
#pragma unroll
    for (int mt = 0; mt < 2; mt++) {
        const int row0 = r0 + mt * 16 + g;
#pragma unroll
        for (int t = 0; t < 5; t++) {
            const int col = c0w + t * 8 + 2 * q;
            scr[row0 * SCR_S + col]       = acc[mt][t][0];
            scr[row0 * SCR_S + col + 1]   = acc[mt][t][1];
            scr[(row0 + 8) * SCR_S + col]     = acc[mt][t][2];
            scr[(row0 + 8) * SCR_S + col + 1] = acc[mt][t][3];
        }
    }
    __syncthreads();

    // ================= Phase 2: prefetch W0 + softmax =================
    const __nv_bfloat16* thbase = g_weT_hi + (size_t)b * HW2 * NP;
    const __nv_bfloat16* tlbase = g_weT_lo + (size_t)b * HW2 * NP;
    auto load_W = [&](int oc, uint32_t ws) {
        const int k0 = oc * 128;
        for (int i = tid; i < 1280; i += 256) {
            int r = i / 10, c = i % 10;
            uint32_t off = (uint32_t)r * SW3 + (uint32_t)c * 16;
            CP16(sb + ws + off, thbase + (size_t)(k0 + r) * NP + c * 8);
            CP16(sb + ws + W_HL + off, tlbase + (size_t)(k0 + r) * NP + c * 8);
        }
    };
    load_W(0, WS0_OFF);
    CP_COMMIT();

    uint32_t* atth = (uint32_t*)(smem + ATTH_OFF);
    uint32_t* attl = (uint32_t*)(smem + ATTL_OFF);
    if (tid < 128) {
        float* row = scr + tid * SCR_S;
        float mx = -1e30f;
        for (int n = 0; n < NW; n++) mx = fmaxf(mx, row[n]);
        float s = 0.f;
        for (int n = 0; n < NW; n++) {
            float e = __expf(row[n] - mx);
            row[n] = e;
            s += e;
        }
        const float inv = 1.f / s;
#pragma unroll
        for (int p = 0; p < 40; p++) {
            float v0 = (2 * p < NW)     ? row[2 * p] * inv     : 0.f;
            float v1 = (2 * p + 1 < NW) ? row[2 * p + 1] * inv : 0.f;
            uint32_t ph, pl;
            split2(v0, v1, ph, pl);
            atth[tid * ATT_S + p] = ph;
            attl[tid * ATT_S + p] = pl;
        }
    }
    __syncthreads();

    // ================= Phase 3: out = att @ weT =================
    const int c0w3 = cg * 64;
    for (int oc = 0; oc < 8; oc++) {
        const int s = oc & 1;
        const uint32_t ws = s ? WS1_OFF : WS0_OFF;
        if (oc < 7) { load_W(oc + 1, (s ^ 1) ? WS1_OFF : WS0_OFF); CP_COMMIT(); }
        if (oc < 7) CP_WAIT1(); else CP_WAIT0();
        __syncthreads();

        float acc2[2][8][4];
#pragma unroll
        for (int mt = 0; mt < 2; mt++)
#pragma unroll
            for (int t = 0; t < 8; t++)
#pragma unroll
                for (int j = 0; j < 4; j++) acc2[mt][t][j] = 0.f;

#pragma unroll
        for (int ks = 0; ks < 5; ks++) {
            const int p0 = ks * 8 + q;
            uint32_t a_h[2][4], a_l[2][4];
#pragma unroll
            for (int mt = 0; mt < 2; mt++) {
                const int rr = r0 + mt * 16 + g;
                a_h[mt][0] = atth[rr * ATT_S + p0];
                a_h[mt][1] = atth[(rr + 8) * ATT_S + p0];
                a_h[mt][2] = atth[rr * ATT_S + p0 + 4];
                a_h[mt][3] = atth[(rr + 8) * ATT_S + p0 + 4];
                a_l[mt][0] = attl[rr * ATT_S + p0];
                a_l[mt][1] = attl[(rr + 8) * ATT_S + p0];
                a_l[mt][2] = attl[rr * ATT_S + p0 + 4];
                a_l[mt][3] = attl[(rr + 8) * ATT_S + p0 + 4];
            }
            const uint32_t kb = (uint32_t)ks * 32;
#pragma unroll
            for (int tp = 0; tp < 4; tp++) {
                uint32_t bo = (uint32_t)(c0w3 + tp * 16) * SW3 +
                              ((uint32_t)((lane >> 4) * 8 + ar)) * SW3 +
                              (uint32_t)((lane >> 3) & 1) * 16 + kb;
                uint32_t b_h[4], b_l[4];
                ldsm4(b_h, sb + ws + bo);
                ldsm4(b_l, sb + ws + W_HL + bo);
#pragma unroll
                for (int mt = 0; mt < 2; mt++) {
                    mma_bf16(acc2[mt][2 * tp],     a_h[mt], b_h[0], b_h[1]);
                    mma_bf16(acc2[mt][2 * tp],     a_h[mt], b_l[0], b_l[1]);
                    mma_bf16(acc2[mt][2 * tp],     a_l[mt], b_h[0], b_h[1]);
                    mma_bf16(acc2[mt][2 * tp + 1], a_h[mt], b_h[2], b_h[3]);
                    mma_bf16(acc2[mt][2 * tp + 1], a_h[mt], b_l[2], b_l[3]);
                    mma_bf16(acc2[mt][2 * tp + 1], a_l[mt], b_h[2], b_h[3]);
                }
            }
        }

        const int k0 = oc * 128;
#pragma unroll
        for (int mt = 0; mt < 2; mt++) {
            float* ob = out + ((size_t)b * CC + c0 + r0 + mt * 16) * HW2 + k0 + c0w3;
#pragma unroll
            for (int t = 0; t < 8; t++) {
                int col = t * 8 + 2 * q;
                *(float2*)&ob[(size_t)g * HW2 + col]       = make_float2(acc2[mt][t][0], acc2[mt][t][1]);
                *(float2*)&ob[(size_t)(g + 8) * HW2 + col] = make_float2(acc2[mt][t][2], acc2[mt][t][3]);
            }
        }
        __syncthreads();
    }
}

// ---------------------------------------------------------------------------
extern "C" void kernel_launch(void* const* d_in, const int* in_sizes, int n_in,
                              void* d_out, int out_size) {
    const float* feat     = (const float*)d_in[0];
    const float* word_emb = (const float*)d_in[1];
    const float* W_fc     = (const float*)d_in[2];
    const float* b_fc     = (const float*)d_in[3];
    float* out            = (float*)d_out;
    (void)in_sizes; (void)n_in; (void)out_size;

    cudaFuncSetAttribute(we_gemm_tc, cudaFuncAttributeMaxDynamicSharedMemorySize, G_SMEM);
    cudaFuncSetAttribute(attn_tc, cudaFuncAttributeMaxDynamicSharedMemorySize, SMEM_ATT);

    split_inputs<<<(A_TASKS + W_TASKS + 255) / 256, 256>>>(word_emb, W_fc);
    we_gemm_tc<<<dim3(HW2 / 128, MP / 128), 256, G_SMEM>>>(b_fc);   // (8, 20)
    transpose_we<<<dim3(HW2 / 64, BB), 256>>>();                    // (16, 32)
    attn_tc<<<dim3(CC / 128, BB), 256, SMEM_ATT>>>(feat, out);      // (4, 32)
}

// round 12
// speedup vs baseline: 2.7405x; 1.1136x over previous
#include <cuda_runtime.h>
#include <cuda_bf16.h>
#include <cstdint>

#define BB   32
#define CC   512
#define HW2  1024
#define NW   77
#define NP   80          // padded n
#define WD   256
#define MP   (BB * NP)   // 2560 padded rows

// ---------------- scratch ----------------
__device__ __nv_bfloat16 g_a_hi[(size_t)MP * WD];
__device__ __nv_bfloat16 g_a_lo[(size_t)MP * WD];
__device__ __nv_bfloat16 g_w_hi[(size_t)HW2 * WD];
__device__ __nv_bfloat16 g_w_lo[(size_t)HW2 * WD];
__device__ __nv_bfloat16 g_we_hi[(size_t)BB * NP * HW2];
__device__ __nv_bfloat16 g_we_lo[(size_t)BB * NP * HW2];
__device__ __nv_bfloat16 g_weT_hi[(size_t)BB * HW2 * NP];
__device__ __nv_bfloat16 g_weT_lo[(size_t)BB * HW2 * NP];

// ---------------- helpers ----------------
__device__ __forceinline__ uint32_t smem_to_u32(const void* p) {
    uint32_t a;
    asm("{ .reg .u64 t; cvta.to.shared.u64 t, %1; cvt.u32.u64 %0, t; }" : "=r"(a) : "l"(p));
    return a;
}
__device__ __forceinline__ void mma_bf16(float* c, const uint32_t* a, uint32_t b0, uint32_t b1) {
    asm volatile(
        "mma.sync.aligned.m16n8k16.row.col.f32.bf16.bf16.f32 "
        "{%0,%1,%2,%3}, {%4,%5,%6,%7}, {%8,%9}, {%0,%1,%2,%3};"
        : "+f"(c[0]), "+f"(c[1]), "+f"(c[2]), "+f"(c[3])
        : "r"(a[0]), "r"(a[1]), "r"(a[2]), "r"(a[3]), "r"(b0), "r"(b1));
}
__device__ __forceinline__ void ldsm4(uint32_t* r, uint32_t addr) {
    asm volatile("ldmatrix.sync.aligned.m8n8.x4.shared.b16 {%0,%1,%2,%3}, [%4];"
        : "=r"(r[0]), "=r"(r[1]), "=r"(r[2]), "=r"(r[3]) : "r"(addr));
}
__device__ __forceinline__ void ldsm2(uint32_t* r, uint32_t addr) {
    asm volatile("ldmatrix.sync.aligned.m8n8.x2.shared.b16 {%0,%1}, [%2];"
        : "=r"(r[0]), "=r"(r[1]) : "r"(addr));
}
__device__ __forceinline__ void split2(float v0, float v1, uint32_t& ph, uint32_t& pl) {
    __nv_bfloat16 h0 = __float2bfloat16(v0), h1 = __float2bfloat16(v1);
    float r0 = v0 - __bfloat162float(h0), r1 = v1 - __bfloat162float(h1);
    __nv_bfloat16 l0 = __float2bfloat16(r0), l1 = __float2bfloat16(r1);
    ph = (uint32_t)__bfloat16_as_ushort(h0) | ((uint32_t)__bfloat16_as_ushort(h1) << 16);
    pl = (uint32_t)__bfloat16_as_ushort(l0) | ((uint32_t)__bfloat16_as_ushort(l1) << 16);
}
#define CP16(dst, src) asm volatile("cp.async.cg.shared.global [%0], [%1], 16;" :: "r"(dst), "l"(src))
#define CP_COMMIT()    asm volatile("cp.async.commit_group;" ::: "memory")
#define CP_WAIT0()     asm volatile("cp.async.wait_group 0;" ::: "memory")
#define CP_WAIT1()     asm volatile("cp.async.wait_group 1;" ::: "memory")

#define SA  144   // 64-wide bf16 tile row stride bytes
#define SW3 176   // phase-3 W row stride bytes (88 bf16)

// ---------------------------------------------------------------------------
// Kernel 0: elementwise bf16 hi/lo split of word_emb (padded) + W_fc
// ---------------------------------------------------------------------------
#define A_TASKS (MP * WD / 4)
#define W_TASKS (HW2 * WD / 4)
__global__ void split_inputs(const float* __restrict__ we_in,
                             const float* __restrict__ Wfc) {
    int idx = blockIdx.x * 256 + threadIdx.x;
    if (idx < A_TASKS) {
        int mp = idx >> 6, c4 = idx & 63;
        int bb = mp / NP, nn = mp % NP;
        float4 v = make_float4(0.f, 0.f, 0.f, 0.f);
        if (nn < NW) v = *(const float4*)(we_in + ((size_t)bb * NW + nn) * WD + c4 * 4);
        uint32_t h0, l0, h1, l1;
        split2(v.x, v.y, h0, l0);
        split2(v.z, v.w, h1, l1);
        *(uint2*)(g_a_hi + (size_t)mp * WD + c4 * 4) = make_uint2(h0, h1);
        *(uint2*)(g_a_lo + (size_t)mp * WD + c4 * 4) = make_uint2(l0, l1);
    } else if (idx < A_TASKS + W_TASKS) {
        int j = idx - A_TASKS;
        int r = j >> 6, c4 = j & 63;
        float4 v = *(const float4*)(Wfc + (size_t)r * WD + c4 * 4);
        uint32_t h0, l0, h1, l1;
        split2(v.x, v.y, h0, l0);
        split2(v.z, v.w, h1, l1);
        *(uint2*)(g_w_hi + (size_t)r * WD + c4 * 4) = make_uint2(h0, h1);
        *(uint2*)(g_w_lo + (size_t)r * WD + c4 * 4) = make_uint2(l0, l1);
    }
}

// ---------------------------------------------------------------------------
// Kernel 1: we = word_emb @ W_fc^T + b_fc (bf16 GEMM, cp.async 2-stage)
// 64-row CTAs, 256 threads, 8 warps = 4 rowgroups(16 rows) x 2 colgroups(64).
// ---------------------------------------------------------------------------
#define G_AH 0
#define G_AL 9216
#define G_BH 18432
#define G_BL 36864
#define G_STAGE 55296
#define G_SMEM  110592

__global__ __launch_bounds__(256, 2) void we_gemm_tc(const float* __restrict__ bfc) {
    extern __shared__ char smem[];
    const uint32_t sb = smem_to_u32(smem);
    const int tid  = threadIdx.x;
    const int wid  = tid >> 5;
    const int lane = tid & 31;
    const int q    = lane & 3;
    const int g    = lane >> 2;
    const int rg   = wid & 3;
    const int cg   = wid >> 2;
    const int m0   = blockIdx.y * 64;
    const int k0   = blockIdx.x * 128;
    const int r0   = rg * 16;
    const int c0w  = cg * 64;

    float acc[8][4];
#pragma unroll
    for (int t = 0; t < 8; t++)
#pragma unroll
        for (int j = 0; j < 4; j++) acc[t][j] = 0.f;

    const int am = lane >> 3;
    const int ar = lane & 7;
    const uint32_t arow = (uint32_t)((am & 1) * 8 + ar) * SA + (uint32_t)(am >> 1) * 16;
    const uint32_t b4row = (uint32_t)((lane >> 4) * 8 + ar) * SA + (uint32_t)((lane >> 3) & 1) * 16;

    auto load_chunk = [&](int ch, int s) {
        const int kc = ch * 64;
        const uint32_t st = sb + (uint32_t)s * G_STAGE;
        for (int i = tid; i < 1024; i += 256) {
            int r = i >> 3, c = i & 7;
            uint32_t off = (uint32_t)r * SA + (uint32_t)c * 16;
            CP16(st + G_BH + off, g_w_hi + (size_t)(k0 + r) * WD + kc + c * 8);
            CP16(st + G_BL + off, g_w_lo + (size_t)(k0 + r) * WD + kc + c * 8);
            if (r < 64) {
                CP16(st + G_AH + off, g_a_hi + (size_t)(m0 + r) * WD + kc + c * 8);
                CP16(st + G_AL + off, g_a_lo + (size_t)(m0 + r) * WD + kc + c * 8);
            }
        }
    };

    load_chunk(0, 0);
    CP_COMMIT();

    for (int ch = 0; ch < 4; ch++) {
        const int s = ch & 1;
        if (ch < 3) { load_chunk(ch + 1, s ^ 1); CP_COMMIT(); }
        if (ch < 3) CP_WAIT1(); else CP_WAIT0();
        __syncthreads();

        const uint32_t st = sb + (uint32_t)s * G_STAGE;
#pragma unroll
        for (int ks = 0; ks < 4; ks++) {
            const uint32_t kb = (uint32_t)ks * 32;
            uint32_t a_h[4], a_l[4];
            {
                uint32_t ao = (uint32_t)r0 * SA + arow + kb;
                ldsm4(a_h, st + G_AH + ao);
                ldsm4(a_l, st + G_AL + ao);
            }
#pragma unroll
            for (int tp = 0; tp < 4; tp++) {
                uint32_t bo = (uint32_t)(c0w + tp * 16) * SA + b4row + kb;
                uint32_t b_h[4], b_l[4];
                ldsm4(b_h, st + G_BH + bo);
                ldsm4(b_l, st + G_BL + bo);
                mma_bf16(acc[2 * tp],     a_h, b_h[0], b_h[1]);
                mma_bf16(acc[2 * tp],     a_h, b_l[0], b_l[1]);
                mma_bf16(acc[2 * tp],     a_l, b_h[0], b_h[1]);
                mma_bf16(acc[2 * tp + 1], a_h, b_h[2], b_h[3]);
                mma_bf16(acc[2 * tp + 1], a_h, b_l[2], b_l[3]);
                mma_bf16(acc[2 * tp + 1], a_l, b_h[2], b_h[3]);
            }
        }
        __syncthreads();
    }

    // epilogue
    const int mp0 = m0 + r0 + g;
    const int mp1 = mp0 + 8;
    const bool v0ok = ((mp0 % NP) < NW);
    const bool v1ok = ((mp1 % NP) < NW);
#pragma unroll
    for (int t = 0; t < 8; t++) {
        const int col = k0 + c0w + t * 8 + 2 * q;
        const float b0 = bfc[col], b1 = bfc[col + 1];
        float v00 = v0ok ? acc[t][0] + b0 : 0.f;
        float v01 = v0ok ? acc[t][1] + b1 : 0.f;
        float v10 = v1ok ? acc[t][2] + b0 : 0.f;
        float v11 = v1ok ? acc[t][3] + b1 : 0.f;
        uint32_t ph, pl;
        split2(v00, v01, ph, pl);
        *(uint32_t*)(g_we_hi + (size_t)mp0 * HW2 + col) = ph;
        *(uint32_t*)(g_we_lo + (size_t)mp0 * HW2 + col) = pl;
        split2(v10, v11, ph, pl);
        *(uint32_t*)(g_we_hi + (size_t)mp1 * HW2 + col) = ph;
        *(uint32_t*)(g_we_lo + (size_t)mp1 * HW2 + col) = pl;
    }
}

// ---------------------------------------------------------------------------
// Kernel 2: transpose splits -> weT[b][k][n]
// ---------------------------------------------------------------------------
__global__ void transpose_we() {
    __shared__ unsigned short sh[NP][66];
    __shared__ unsigned short sl[NP][66];
    const int tid = threadIdx.x;
    const int k0  = blockIdx.x * 64;
    const int b   = blockIdx.y;

    for (int i = tid; i < NP * 32; i += 256) {
        int n = i >> 5, w = i & 31;
        uint32_t vh = *(const uint32_t*)(g_we_hi + ((size_t)b * NP + n) * HW2 + k0 + 2 * w);
        uint32_t vl = *(const uint32_t*)(g_we_lo + ((size_t)b * NP + n) * HW2 + k0 + 2 * w);
        sh[n][2 * w] = (unsigned short)(vh & 0xffff); sh[n][2 * w + 1] = (unsigned short)(vh >> 16);
        sl[n][2 * w] = (unsigned short)(vl & 0xffff); sl[n][2 * w + 1] = (unsigned short)(vl >> 16);
    }
    __syncthreads();
    for (int i = tid; i < 64 * 40; i += 256) {
        int k = i / 40, j = i % 40;
        uint32_t oh = (uint32_t)sh[2 * j][k] | ((uint32_t)sh[2 * j + 1][k] << 16);
        uint32_t ol = (uint32_t)sl[2 * j][k] | ((uint32_t)sl[2 * j + 1][k] << 16);
        size_t off = ((size_t)b * HW2 + k0 + k) * NP;
        *(uint32_t*)(g_weT_hi + off + 2 * j) = oh;
        *(uint32_t*)(g_weT_lo + off + 2 * j) = ol;
    }
}

// ---------------------------------------------------------------------------
// Kernel 3: fused attention, 64-channel-row CTAs, 256 threads,
// 8 warps = 4 rowgroups(16 rows) x 2 colgroups. grid = (8, 32) = 256 CTAs.
// ---------------------------------------------------------------------------
#define P1_AH 0
#define P1_AL 9216
#define P1_BH 18432
#define P1_BL 29952
#define P1_STAGE 41472
// phase-2/3 overlays
#define ATTH_OFF 0          // uint32 [64][41]
#define ATTL_OFF 10496
#define SCR_OFF  20992      // fp32 [64][81]
#define WS1_OFF  20992      // overlays SCR (used after softmax)
#define WS0_OFF  66048
#define W_HL     22528
#define ATT_S    41
#define SCR_S    81
#define SMEM_ATT 111104

__global__ __launch_bounds__(256, 2) void attn_tc(const float* __restrict__ feat,
                                                  float* __restrict__ out) {
    extern __shared__ char smem[];
    const uint32_t sb = smem_to_u32(smem);
    const int tid  = threadIdx.x;
    const int wid  = tid >> 5;
    const int lane = tid & 31;
    const int q    = lane & 3;
    const int g    = lane >> 2;
    const int rg   = wid & 3;
    const int cg   = wid >> 2;
    const int b    = blockIdx.y;
    const int c0   = blockIdx.x * 64;
    const int r0   = rg * 16;

    const float* fb = feat + ((size_t)b * CC + c0) * HW2;
    const __nv_bfloat16* weh = g_we_hi + (size_t)b * NP * HW2;
    const __nv_bfloat16* wel = g_we_lo + (size_t)b * NP * HW2;

    const int am = lane >> 3;
    const int ar = lane & 7;
    const uint32_t arow = (uint32_t)((am & 1) * 8 + ar) * SA + (uint32_t)(am >> 1) * 16;
    const uint32_t b4row = (uint32_t)((lane >> 4) * 8 + ar) * SA + (uint32_t)((lane >> 3) & 1) * 16;
    const uint32_t b2row = (uint32_t)ar * SA + (uint32_t)((lane >> 3) & 1) * 16;

    // ---- phase-1 loaders: A 64 rows x 64 cols (4 threads/row, 16 cols) ----
    const int lr = tid >> 2, lh = tid & 3;
    auto load_A_regs = [&](int ch, float4* pf) {
        const float* src = fb + (size_t)lr * HW2 + ch * 64 + lh * 16;
#pragma unroll
        for (int i = 0; i < 4; i++) pf[i] = *(const float4*)(src + i * 4);
    };
    auto store_A = [&](int s, const float4* pf) {
        char* ph_ = smem + s * P1_STAGE + P1_AH + lr * SA + lh * 32;
        char* pl_ = smem + s * P1_STAGE + P1_AL + lr * SA + lh * 32;
#pragma unroll
        for (int i = 0; i < 4; i++) {
            uint32_t p0h, p0l, p1h, p1l;
            split2(pf[i].x, pf[i].y, p0h, p0l);
            split2(pf[i].z, pf[i].w, p1h, p1l);
            *(uint32_t*)(ph_ + i * 8)     = p0h;
            *(uint32_t*)(ph_ + i * 8 + 4) = p1h;
            *(uint32_t*)(pl_ + i * 8)     = p0l;
            *(uint32_t*)(pl_ + i * 8 + 4) = p1l;
        }
    };
    auto load_B = [&](int ch, int s) {
        const int kc = ch * 64;
        const uint32_t st = sb + (uint32_t)s * P1_STAGE;
        for (int i = tid; i < 640; i += 256) {
            int r = i >> 3, cch = i & 7;
            uint32_t off = (uint32_t)r * SA + (uint32_t)cch * 16;
            CP16(st + P1_BH + off, weh + (size_t)r * HW2 + kc + cch * 8);
            CP16(st + P1_BL + off, wel + (size_t)r * HW2 + kc + cch * 8);
        }
    };

    // ================= Phase 1: scores =================
    float acc[5][4];
#pragma unroll
    for (int t = 0; t < 5; t++)
#pragma unroll
        for (int j = 0; j < 4; j++) acc[t][j] = 0.f;

    const int c0w = cg * 40;

    float4 pf[4];
    load_A_regs(0, pf);
    load_B(0, 0);
    CP_COMMIT();
    store_A(0, pf);

    for (int it = 0; it < 16; it++) {
        const int s = it & 1;
        if (it < 15) {
            load_A_regs(it + 1, pf);
            load_B(it + 1, s ^ 1);
            CP_COMMIT();
        }
        if (it < 15) CP_WAIT1(); else CP_WAIT0();
        __syncthreads();

        const uint32_t st = sb + (uint32_t)s * P1_STAGE;
#pragma unroll
        for (int ks = 0; ks < 4; ks++) {
            const uint32_t kb = (uint32_t)ks * 32;
            uint32_t a_h[4], a_l[4];
            {
                uint32_t ao = (uint32_t)r0 * SA + arow + kb;
                ldsm4(a_h, st + P1_AH + ao);
                ldsm4(a_l, st + P1_AL + ao);
            }
            uint32_t b_h[2][4], b_l[2][4], b2h[2], b2l[2];
#pragma unroll
            for (int tp = 0; tp < 2; tp++) {
                uint32_t bo = (uint32_t)(c0w + tp * 16) * SA + b4row + kb;
                ldsm4(b_h[tp], st + P1_BH + bo);
                ldsm4(b_l[tp], st + P1_BL + bo);
            }
            {
                uint32_t bo = (uint32_t)(c0w + 32) * SA + b2row + kb;
                ldsm2(b2h, st + P1_BH + bo);
                ldsm2(b2l, st + P1_BL + bo);
            }
#pragma unroll
            for (int tp = 0; tp < 2; tp++) {
                mma_bf16(acc[2 * tp],     a_h, b_h[tp][0], b_h[tp][1]);
                mma_bf16(acc[2 * tp],     a_h, b_l[tp][0], b_l[tp][1]);
                mma_bf16(acc[2 * tp],     a_l, b_h[tp][0], b_h[tp][1]);
                mma_bf16(acc[2 * tp + 1], a_h, b_h[tp][2], b_h[tp][3]);
                mma_bf16(acc[2 * tp + 1], a_h, b_l[tp][2], b_l[tp][3]);
                mma_bf16(acc[2 * tp + 1], a_l, b_h[tp][2], b_h[tp][3]);
            }
            mma_bf16(acc[4], a_h, b2h[0], b2h[1]);
            mma_bf16(acc[4], a_h, b2l[0], b2l[1]);
            mma_bf16(acc[4], a_l, b2h[0], b2h[1]);
        }
        if (it < 15) store_A(s ^ 1, pf);
        __syncthreads();
    }

    // ---- write scores ----
    float* scr = (float*)(smem + SCR_OFF);
    {
        const int row0 = r0 + g;
#pragma unroll
        for (int t = 0; t < 5; t++) {
            const int col = c0w + t * 8 + 2 * q;
            scr[row0 * SCR_S + col]       = acc[t][0];
            scr[row0 * SCR_S + col + 1]   = acc[t][1];
            scr[(row0 + 8) * SCR_S + col]     = acc[t][2];
            scr[(row0 + 8) * SCR_S + col + 1] = acc[t][3];
        }
    }
    __syncthreads();

    // ================= Phase 2: prefetch W0 + softmax (quad per row) =========
    const __nv_bfloat16* thbase = g_weT_hi + (size_t)b * HW2 * NP;
    const __nv_bfloat16* tlbase = g_weT_lo + (size_t)b * HW2 * NP;
    auto load_W = [&](int oc, uint32_t ws) {
        const int k0 = oc * 128;
        for (int i = tid; i < 1280; i += 256) {
            int r = i / 10, c = i % 10;
            uint32_t off = (uint32_t)r * SW3 + (uint32_t)c * 16;
            CP16(sb + ws + off, thbase + (size_t)(k0 + r) * NP + c * 8);
            CP16(sb + ws + W_HL + off, tlbase + (size_t)(k0 + r) * NP + c * 8);
        }
    };
    load_W(0, WS0_OFF);
    CP_COMMIT();

    uint32_t* atth = (uint32_t*)(smem + ATTH_OFF);
    uint32_t* attl = (uint32_t*)(smem + ATTL_OFF);
    {
        const int row = tid >> 2, t4 = tid & 3;
        float* rowp = scr + row * SCR_S;
        const int n0 = t4 * 20;
        const int n1 = (n0 + 20 < NW) ? n0 + 20 : NW;
        float mx = -1e30f;
        for (int n = n0; n < n1; n++) mx = fmaxf(mx, rowp[n]);
        mx = fmaxf(mx, __shfl_xor_sync(0xffffffffu, mx, 1));
        mx = fmaxf(mx, __shfl_xor_sync(0xffffffffu, mx, 2));
        float s = 0.f;
        for (int n = n0; n < n1; n++) {
            float e = __expf(rowp[n] - mx);
            rowp[n] = e;
            s += e;
        }
        s += __shfl_xor_sync(0xffffffffu, s, 1);
        s += __shfl_xor_sync(0xffffffffu, s, 2);
        const float inv = 1.f / s;
#pragma unroll
        for (int p = t4 * 10; p < t4 * 10 + 10; p++) {
            float v0 = (2 * p < NW)     ? rowp[2 * p] * inv     : 0.f;
            float v1 = (2 * p + 1 < NW) ? rowp[2 * p + 1] * inv : 0.f;
            uint32_t ph, pl;
            split2(v0, v1, ph, pl);
            atth[row * ATT_S + p] = ph;
            attl[row * ATT_S + p] = pl;
        }
    }
    __syncthreads();

    // ================= Phase 3: out = att @ weT =================
    const int c0w3 = cg * 64;
    for (int oc = 0; oc < 8; oc++) {
        const int s = oc & 1;
        const uint32_t ws = s ? WS1_OFF : WS0_OFF;
        if (oc < 7) { load_W(oc + 1, (s ^ 1) ? WS1_OFF : WS0_OFF); CP_COMMIT(); }
        if (oc < 7) CP_WAIT1(); else CP_WAIT0();
        __syncthreads();

        float acc2[8][4];
#pragma unroll
        for (int t = 0; t < 8; t++)
#pragma unroll
            for (int j = 0; j < 4; j++) acc2[t][j] = 0.f;

#pragma unroll
        for (int ks = 0; ks < 5; ks++) {
            const int p0 = ks * 8 + q;
            const int rr = r0 + g;
            uint32_t a_h[4], a_l[4];
            a_h[0] = atth[rr * ATT_S + p0];
            a_h[1] = atth[(rr + 8) * ATT_S + p0];
            a_h[2] = atth[rr * ATT_S + p0 + 4];
            a_h[3] = atth[(rr + 8) * ATT_S + p0 + 4];
            a_l[0] = attl[rr * ATT_S + p0];
            a_l[1] = attl[(rr + 8) * ATT_S + p0];
            a_l[2] = attl[rr * ATT_S + p0 + 4];
            a_l[3] = attl[(rr + 8) * ATT_S + p0 + 4];
            const uint32_t kb = (uint32_t)ks * 32;
#pragma unroll
            for (int tp = 0; tp < 4; tp++) {
                uint32_t bo = (uint32_t)(c0w3 + tp * 16) * SW3 +
                              ((uint32_t)((lane >> 4) * 8 + ar)) * SW3 +
                              (uint32_t)((lane >> 3) & 1) * 16 + kb;
                uint32_t b_h[4], b_l[4];
                ldsm4(b_h, sb + ws + bo);
                ldsm4(b_l, sb + ws + W_HL + bo);
                mma_bf16(acc2[2 * tp],     a_h, b_h[0], b_h[1]);
                mma_bf16(acc2[2 * tp],     a_h, b_l[0], b_l[1]);
                mma_bf16(acc2[2 * tp],     a_l, b_h[0], b_h[1]);
                mma_bf16(acc2[2 * tp + 1], a_h, b_h[2], b_h[3]);
                mma_bf16(acc2[2 * tp + 1], a_h, b_l[2], b_l[3]);
                mma_bf16(acc2[2 * tp + 1], a_l, b_h[2], b_h[3]);
            }
        }

        const int k0 = oc * 128;
        float* ob = out + ((size_t)b * CC + c0 + r0) * HW2 + k0 + c0w3;
#pragma unroll
        for (int t = 0; t < 8; t++) {
            int col = t * 8 + 2 * q;
            *(float2*)&ob[(size_t)g * HW2 + col]       = make_float2(acc2[t][0], acc2[t][1]);
            *(float2*)&ob[(size_t)(g + 8) * HW2 + col] = make_float2(acc2[t][2], acc2[t][3]);
        }
        __syncthreads();
    }
}

// ---------------------------------------------------------------------------
extern "C" void kernel_launch(void* const* d_in, const int* in_sizes, int n_in,
                              void* d_out, int out_size) {
    const float* feat     = (const float*)d_in[0];
    const float* word_emb = (const float*)d_in[1];
    const float* W_fc     = (const float*)d_in[2];
    const float* b_fc     = (const float*)d_in[3];
    float* out            = (float*)d_out;
    (void)in_sizes; (void)n_in; (void)out_size;

    cudaFuncSetAttribute(we_gemm_tc, cudaFuncAttributeMaxDynamicSharedMemorySize, G_SMEM);
    cudaFuncSetAttribute(attn_tc, cudaFuncAttributeMaxDynamicSharedMemorySize, SMEM_ATT);

    split_inputs<<<(A_TASKS + W_TASKS + 255) / 256, 256>>>(word_emb, W_fc);
    we_gemm_tc<<<dim3(HW2 / 128, MP / 64), 256, G_SMEM>>>(b_fc);    // (8, 40)
    transpose_we<<<dim3(HW2 / 64, BB), 256>>>();                    // (16, 32)
    attn_tc<<<dim3(CC / 64, BB), 256, SMEM_ATT>>>(feat, out);       // (8, 32)
}

// round 13
// speedup vs baseline: 2.8423x; 1.0371x over previous
#include <cuda_runtime.h>
#include <cuda_bf16.h>
#include <cstdint>

#define BB   32
#define CC   512
#define HW2  1024
#define NW   77
#define NP   80          // padded n
#define WD   256
#define MP   (BB * NP)   // 2560 padded rows

// ---------------- scratch ----------------
__device__ __nv_bfloat16 g_a_hi[(size_t)MP * WD];
__device__ __nv_bfloat16 g_a_lo[(size_t)MP * WD];
__device__ __nv_bfloat16 g_w_hi[(size_t)HW2 * WD];
__device__ __nv_bfloat16 g_w_lo[(size_t)HW2 * WD];
__device__ __nv_bfloat16 g_we_hi[(size_t)BB * NP * HW2];
__device__ __nv_bfloat16 g_we_lo[(size_t)BB * NP * HW2];
__device__ __nv_bfloat16 g_weT_hi[(size_t)BB * HW2 * NP];
__device__ __nv_bfloat16 g_weT_lo[(size_t)BB * HW2 * NP];

// ---------------- helpers ----------------
__device__ __forceinline__ uint32_t smem_to_u32(const void* p) {
    uint32_t a;
    asm("{ .reg .u64 t; cvta.to.shared.u64 t, %1; cvt.u32.u64 %0, t; }" : "=r"(a) : "l"(p));
    return a;
}
__device__ __forceinline__ void mma_bf16(float* c, const uint32_t* a, uint32_t b0, uint32_t b1) {
    asm volatile(
        "mma.sync.aligned.m16n8k16.row.col.f32.bf16.bf16.f32 "
        "{%0,%1,%2,%3}, {%4,%5,%6,%7}, {%8,%9}, {%0,%1,%2,%3};"
        : "+f"(c[0]), "+f"(c[1]), "+f"(c[2]), "+f"(c[3])
        : "r"(a[0]), "r"(a[1]), "r"(a[2]), "r"(a[3]), "r"(b0), "r"(b1));
}
__device__ __forceinline__ void ldsm4(uint32_t* r, uint32_t addr) {
    asm volatile("ldmatrix.sync.aligned.m8n8.x4.shared.b16 {%0,%1,%2,%3}, [%4];"
        : "=r"(r[0]), "=r"(r[1]), "=r"(r[2]), "=r"(r[3]) : "r"(addr));
}
__device__ __forceinline__ void split2(float v0, float v1, uint32_t& ph, uint32_t& pl) {
    __nv_bfloat16 h0 = __float2bfloat16(v0), h1 = __float2bfloat16(v1);
    float r0 = v0 - __bfloat162float(h0), r1 = v1 - __bfloat162float(h1);
    __nv_bfloat16 l0 = __float2bfloat16(r0), l1 = __float2bfloat16(r1);
    ph = (uint32_t)__bfloat16_as_ushort(h0) | ((uint32_t)__bfloat16_as_ushort(h1) << 16);
    pl = (uint32_t)__bfloat16_as_ushort(l0) | ((uint32_t)__bfloat16_as_ushort(l1) << 16);
}
#define CP16(dst, src) asm volatile("cp.async.cg.shared.global [%0], [%1], 16;" :: "r"(dst), "l"(src))
#define CP_COMMIT()    asm volatile("cp.async.commit_group;" ::: "memory")
#define CP_WAIT0()     asm volatile("cp.async.wait_group 0;" ::: "memory")
#define CP_WAIT1()     asm volatile("cp.async.wait_group 1;" ::: "memory")

#define SA  144
#define SW3 176

// ---------------------------------------------------------------------------
// Kernel 0: elementwise bf16 hi/lo split of word_emb (padded) + W_fc
// ---------------------------------------------------------------------------
#define A_TASKS (MP * WD / 4)
#define W_TASKS (HW2 * WD / 4)
__global__ void split_inputs(const float* __restrict__ we_in,
                             const float* __restrict__ Wfc) {
    int idx = blockIdx.x * 256 + threadIdx.x;
    if (idx < A_TASKS) {
        int mp = idx >> 6, c4 = idx & 63;
        int bb = mp / NP, nn = mp % NP;
        float4 v = make_float4(0.f, 0.f, 0.f, 0.f);
        if (nn < NW) v = *(const float4*)(we_in + ((size_t)bb * NW + nn) * WD + c4 * 4);
        uint32_t h0, l0, h1, l1;
        split2(v.x, v.y, h0, l0);
        split2(v.z, v.w, h1, l1);
        *(uint2*)(g_a_hi + (size_t)mp * WD + c4 * 4) = make_uint2(h0, h1);
        *(uint2*)(g_a_lo + (size_t)mp * WD + c4 * 4) = make_uint2(l0, l1);
    } else if (idx < A_TASKS + W_TASKS) {
        int j = idx - A_TASKS;
        int r = j >> 6, c4 = j & 63;
        float4 v = *(const float4*)(Wfc + (size_t)r * WD + c4 * 4);
        uint32_t h0, l0, h1, l1;
        split2(v.x, v.y, h0, l0);
        split2(v.z, v.w, h1, l1);
        *(uint2*)(g_w_hi + (size_t)r * WD + c4 * 4) = make_uint2(h0, h1);
        *(uint2*)(g_w_lo + (size_t)r * WD + c4 * 4) = make_uint2(l0, l1);
    }
}

// ---------------------------------------------------------------------------
// Kernel 1: we = word_emb @ W_fc^T + b_fc (bf16 GEMM, cp.async 2-stage)
// (unchanged from R12 — 64-row CTAs, 8 warps = 4rg x 2cg)
// ---------------------------------------------------------------------------
#define G_AH 0
#define G_AL 9216
#define G_BH 18432
#define G_BL 36864
#define G_STAGE 55296
#define G_SMEM  110592

__global__ __launch_bounds__(256, 2) void we_gemm_tc(const float* __restrict__ bfc) {
    extern __shared__ char smem[];
    const uint32_t sb = smem_to_u32(smem);
    const int tid  = threadIdx.x;
    const int wid  = tid >> 5;
    const int lane = tid & 31;
    const int q    = lane & 3;
    const int g    = lane >> 2;
    const int rg   = wid & 3;
    const int cg   = wid >> 2;
    const int m0   = blockIdx.y * 64;
    const int k0   = blockIdx.x * 128;
    const int r0   = rg * 16;
    const int c0w  = cg * 64;

    float acc[8][4];
#pragma unroll
    for (int t = 0; t < 8; t++)
#pragma unroll
        for (int j = 0; j < 4; j++) acc[t][j] = 0.f;

    const int am = lane >> 3;
    const int ar = lane & 7;
    const uint32_t arow = (uint32_t)((am & 1) * 8 + ar) * SA + (uint32_t)(am >> 1) * 16;
    const uint32_t b4row = (uint32_t)((lane >> 4) * 8 + ar) * SA + (uint32_t)((lane >> 3) & 1) * 16;

    auto load_chunk = [&](int ch, int s) {
        const int kc = ch * 64;
        const uint32_t st = sb + (uint32_t)s * G_STAGE;
        for (int i = tid; i < 1024; i += 256) {
            int r = i >> 3, c = i & 7;
            uint32_t off = (uint32_t)r * SA + (uint32_t)c * 16;
            CP16(st + G_BH + off, g_w_hi + (size_t)(k0 + r) * WD + kc + c * 8);
            CP16(st + G_BL + off, g_w_lo + (size_t)(k0 + r) * WD + kc + c * 8);
            if (r < 64) {
                CP16(st + G_AH + off, g_a_hi + (size_t)(m0 + r) * WD + kc + c * 8);
                CP16(st + G_AL + off, g_a_lo + (size_t)(m0 + r) * WD + kc + c * 8);
            }
        }
    };

    load_chunk(0, 0);
    CP_COMMIT();

    for (int ch = 0; ch < 4; ch++) {
        const int s = ch & 1;
        if (ch < 3) { load_chunk(ch + 1, s ^ 1); CP_COMMIT(); }
        if (ch < 3) CP_WAIT1(); else CP_WAIT0();
        __syncthreads();

        const uint32_t st = sb + (uint32_t)s * G_STAGE;
#pragma unroll
        for (int ks = 0; ks < 4; ks++) {
            const uint32_t kb = (uint32_t)ks * 32;
            uint32_t a_h[4], a_l[4];
            {
                uint32_t ao = (uint32_t)r0 * SA + arow + kb;
                ldsm4(a_h, st + G_AH + ao);
                ldsm4(a_l, st + G_AL + ao);
            }
#pragma unroll
            for (int tp = 0; tp < 4; tp++) {
                uint32_t bo = (uint32_t)(c0w + tp * 16) * SA + b4row + kb;
                uint32_t b_h[4], b_l[4];
                ldsm4(b_h, st + G_BH + bo);
                ldsm4(b_l, st + G_BL + bo);
                mma_bf16(acc[2 * tp],     a_h, b_h[0], b_h[1]);
                mma_bf16(acc[2 * tp],     a_h, b_l[0], b_l[1]);
                mma_bf16(acc[2 * tp],     a_l, b_h[0], b_h[1]);
                mma_bf16(acc[2 * tp + 1], a_h, b_h[2], b_h[3]);
                mma_bf16(acc[2 * tp + 1], a_h, b_l[2], b_l[3]);
                mma_bf16(acc[2 * tp + 1], a_l, b_h[2], b_h[3]);
            }
        }
        __syncthreads();
    }

    const int mp0 = m0 + r0 + g;
    const int mp1 = mp0 + 8;
    const bool v0ok = ((mp0 % NP) < NW);
    const bool v1ok = ((mp1 % NP) < NW);
#pragma unroll
    for (int t = 0; t < 8; t++) {
        const int col = k0 + c0w + t * 8 + 2 * q;
        const float b0 = bfc[col], b1 = bfc[col + 1];
        float v00 = v0ok ? acc[t][0] + b0 : 0.f;
        float v01 = v0ok ? acc[t][1] + b1 : 0.f;
        float v10 = v1ok ? acc[t][2] + b0 : 0.f;
        float v11 = v1ok ? acc[t][3] + b1 : 0.f;
        uint32_t ph, pl;
        split2(v00, v01, ph, pl);
        *(uint32_t*)(g_we_hi + (size_t)mp0 * HW2 + col) = ph;
        *(uint32_t*)(g_we_lo + (size_t)mp0 * HW2 + col) = pl;
        split2(v10, v11, ph, pl);
        *(uint32_t*)(g_we_hi + (size_t)mp1 * HW2 + col) = ph;
        *(uint32_t*)(g_we_lo + (size_t)mp1 * HW2 + col) = pl;
    }
}

// ---------------------------------------------------------------------------
// Kernel 2: transpose splits -> weT[b][k][n]
// ---------------------------------------------------------------------------
__global__ void transpose_we() {
    __shared__ unsigned short sh[NP][66];
    __shared__ unsigned short sl[NP][66];
    const int tid = threadIdx.x;
    const int k0  = blockIdx.x * 64;
    const int b   = blockIdx.y;

    for (int i = tid; i < NP * 32; i += 256) {
        int n = i >> 5, w = i & 31;
        uint32_t vh = *(const uint32_t*)(g_we_hi + ((size_t)b * NP + n) * HW2 + k0 + 2 * w);
        uint32_t vl = *(const uint32_t*)(g_we_lo + ((size_t)b * NP + n) * HW2 + k0 + 2 * w);
        sh[n][2 * w] = (unsigned short)(vh & 0xffff); sh[n][2 * w + 1] = (unsigned short)(vh >> 16);
        sl[n][2 * w] = (unsigned short)(vl & 0xffff); sl[n][2 * w + 1] = (unsigned short)(vl >> 16);
    }
    __syncthreads();
    for (int i = tid; i < 64 * 40; i += 256) {
        int k = i / 40, j = i % 40;
        uint32_t oh = (uint32_t)sh[2 * j][k] | ((uint32_t)sh[2 * j + 1][k] << 16);
        uint32_t ol = (uint32_t)sl[2 * j][k] | ((uint32_t)sl[2 * j + 1][k] << 16);
        size_t off = ((size_t)b * HW2 + k0 + k) * NP;
        *(uint32_t*)(g_weT_hi + off + 2 * j) = oh;
        *(uint32_t*)(g_weT_lo + off + 2 * j) = ol;
    }
}

// ---------------------------------------------------------------------------
// Kernel 3: fused attention, 64-row CTAs, 256 threads.
// Phase 1: 8 warps = 2 rowgroups x 2 colgroups x 2 K-halves (tile 32x40x32)
//          partial scores -> two smem buffers, summed in softmax.
// Phase 3: 8 warps = 2 rowgroups x 4 colgroups (tile 32x32), no K-split.
// ---------------------------------------------------------------------------
#define P1_AH 0
#define P1_AL 9216
#define P1_BH 18432
#define P1_BL 29952
#define P1_STAGE 41472
// overlays
#define ATTH_OFF 0
#define ATTL_OFF 10496
#define SCR0_OFF 20992      // fp32 [64][81]
#define SCR1_OFF 41984      // fp32 [64][81]
#define WS1_OFF  20992      // W stage 1 overlays scr after softmax
#define WS0_OFF  66048
#define W_HL     22528
#define ATT_S    41
#define SCR_S    81
#define SMEM_ATT 111104

__global__ __launch_bounds__(256, 2) void attn_tc(const float* __restrict__ feat,
                                                  float* __restrict__ out) {
    extern __shared__ char smem[];
    const uint32_t sb = smem_to_u32(smem);
    const int tid  = threadIdx.x;
    const int wid  = tid >> 5;
    const int lane = tid & 31;
    const int q    = lane & 3;
    const int g    = lane >> 2;
    const int b    = blockIdx.y;
    const int c0   = blockIdx.x * 64;

    // phase-1 warp roles
    const int rg1 = wid & 1;          // 0..1 -> 32 rows
    const int cg1 = (wid >> 1) & 1;   // 0..1 -> 40 cols
    const int kh1 = wid >> 2;         // 0..1 -> K half of 64-chunk
    const int r01 = rg1 * 32;
    const int c0w = cg1 * 40;

    const float* fb = feat + ((size_t)b * CC + c0) * HW2;
    const __nv_bfloat16* weh = g_we_hi + (size_t)b * NP * HW2;
    const __nv_bfloat16* wel = g_we_lo + (size_t)b * NP * HW2;

    const int am = lane >> 3;
    const int ar = lane & 7;
    const uint32_t arow = (uint32_t)((am & 1) * 8 + ar) * SA + (uint32_t)(am >> 1) * 16;
    const uint32_t b4row = (uint32_t)((lane >> 4) * 8 + ar) * SA + (uint32_t)((lane >> 3) & 1) * 16;
    // combined hi/lo tail-n8 ldsm4: lanes 0-15 -> BH, lanes 16-31 -> BL
    const uint32_t cmb_base = (uint32_t)((lane < 16) ? P1_BH : P1_BL) +
                              (uint32_t)(c0w + 32 + ar) * SA +
                              (uint32_t)((lane >> 3) & 1) * 16;

    // ---- phase-1 loaders: A 64 rows x 64 cols (4 threads/row) ----
    const int lr = tid >> 2, lh = tid & 3;
    auto load_A_regs = [&](int ch, float4* pf) {
        const float* src = fb + (size_t)lr * HW2 + ch * 64 + lh * 16;
#pragma unroll
        for (int i = 0; i < 4; i++) pf[i] = *(const float4*)(src + i * 4);
    };
    auto store_A = [&](int s, const float4* pf) {
        uint32_t h[8], l[8];
#pragma unroll
        for (int i = 0; i < 4; i++) {
            split2(pf[i].x, pf[i].y, h[2 * i], l[2 * i]);
            split2(pf[i].z, pf[i].w, h[2 * i + 1], l[2 * i + 1]);
        }
        uint4* ph_ = (uint4*)(smem + s * P1_STAGE + P1_AH + lr * SA + lh * 32);
        uint4* pl_ = (uint4*)(smem + s * P1_STAGE + P1_AL + lr * SA + lh * 32);
        ph_[0] = make_uint4(h[0], h[1], h[2], h[3]);
        ph_[1] = make_uint4(h[4], h[5], h[6], h[7]);
        pl_[0] = make_uint4(l[0], l[1], l[2], l[3]);
        pl_[1] = make_uint4(l[4], l[5], l[6], l[7]);
    };
    auto load_B = [&](int ch, int s) {
        const int kc = ch * 64;
        const uint32_t st = sb + (uint32_t)s * P1_STAGE;
        for (int i = tid; i < 640; i += 256) {
            int r = i >> 3, cch = i & 7;
            uint32_t off = (uint32_t)r * SA + (uint32_t)cch * 16;
            CP16(st + P1_BH + off, weh + (size_t)r * HW2 + kc + cch * 8);
            CP16(st + P1_BL + off, wel + (size_t)r * HW2 + kc + cch * 8);
        }
    };

    // ================= Phase 1: partial scores (K-split) =================
    float acc[2][5][4];
#pragma unroll
    for (int mt = 0; mt < 2; mt++)
#pragma unroll
        for (int t = 0; t < 5; t++)
#pragma unroll
            for (int j = 0; j < 4; j++) acc[mt][t][j] = 0.f;

    float4 pf[4];
    load_A_regs(0, pf);
    load_B(0, 0);
    CP_COMMIT();
    store_A(0, pf);

    for (int it = 0; it < 16; it++) {
        const int s = it & 1;
        if (it < 15) {
            load_A_regs(it + 1, pf);
            load_B(it + 1, s ^ 1);
            CP_COMMIT();
        }
        if (it < 15) CP_WAIT1(); else CP_WAIT0();
        __syncthreads();

        const uint32_t st = sb + (uint32_t)s * P1_STAGE;
#pragma unroll
        for (int ks = 0; ks < 2; ks++) {
            const uint32_t kb = (uint32_t)(kh1 * 64 + ks * 32);
            uint32_t a_h[2][4], a_l[2][4];
#pragma unroll
            for (int mt = 0; mt < 2; mt++) {
                uint32_t ao = (uint32_t)(r01 + mt * 16) * SA + arow + kb;
                ldsm4(a_h[mt], st + P1_AH + ao);
                ldsm4(a_l[mt], st + P1_AL + ao);
            }
            uint32_t b_h[2][4], b_l[2][4], bc[4];
#pragma unroll
            for (int tp = 0; tp < 2; tp++) {
                uint32_t bo = (uint32_t)(c0w + tp * 16) * SA + b4row + kb;
                ldsm4(b_h[tp], st + P1_BH + bo);
                ldsm4(b_l[tp], st + P1_BL + bo);
            }
            ldsm4(bc, st + cmb_base + kb);   // bc[0..1]=hi, bc[2..3]=lo
#pragma unroll
            for (int mt = 0; mt < 2; mt++) {
#pragma unroll
                for (int tp = 0; tp < 2; tp++) {
                    mma_bf16(acc[mt][2 * tp],     a_h[mt], b_h[tp][0], b_h[tp][1]);
                    mma_bf16(acc[mt][2 * tp],     a_h[mt], b_l[tp][0], b_l[tp][1]);
                    mma_bf16(acc[mt][2 * tp],     a_l[mt], b_h[tp][0], b_h[tp][1]);
                    mma_bf16(acc[mt][2 * tp + 1], a_h[mt], b_h[tp][2], b_h[tp][3]);
                    mma_bf16(acc[mt][2 * tp + 1], a_h[mt], b_l[tp][2], b_l[tp][3]);
                    mma_bf16(acc[mt][2 * tp + 1], a_l[mt], b_h[tp][2], b_h[tp][3]);
                }
                mma_bf16(acc[mt][4], a_h[mt], bc[0], bc[1]);
                mma_bf16(acc[mt][4], a_h[mt], bc[2], bc[3]);
                mma_bf16(acc[mt][4], a_l[mt], bc[0], bc[1]);
            }
        }
        if (it < 15) store_A(s ^ 1, pf);
        __syncthreads();
    }

    // ---- write partial scores (per K-half buffer) ----
    float* myscr = (float*)(smem + (kh1 ? SCR1_OFF : SCR0_OFF));
#pragma unroll
    for (int mt = 0; mt < 2; mt++) {
        const int row0 = r01 + mt * 16 + g;
#pragma unroll
        for (int t = 0; t < 5; t++) {
            const int col = c0w + t * 8 + 2 * q;
            myscr[row0 * SCR_S + col]       = acc[mt][t][0];
            myscr[row0 * SCR_S + col + 1]   = acc[mt][t][1];
            myscr[(row0 + 8) * SCR_S + col]     = acc[mt][t][2];
            myscr[(row0 + 8) * SCR_S + col + 1] = acc[mt][t][3];
        }
    }
    __syncthreads();

    // ================= Phase 2: prefetch W0 + softmax =================
    const __nv_bfloat16* thbase = g_weT_hi + (size_t)b * HW2 * NP;
    const __nv_bfloat16* tlbase = g_weT_lo + (size_t)b * HW2 * NP;
    auto load_W = [&](int oc, uint32_t ws) {
        const int k0 = oc * 128;
        for (int i = tid; i < 1280; i += 256) {
            int r = i / 10, c = i % 10;
            uint32_t off = (uint32_t)r * SW3 + (uint32_t)c * 16;
            CP16(sb + ws + off, thbase + (size_t)(k0 + r) * NP + c * 8);
            CP16(sb + ws + W_HL + off, tlbase + (size_t)(k0 + r) * NP + c * 8);
        }
    };
    load_W(0, WS0_OFF);
    CP_COMMIT();

    uint32_t* atth = (uint32_t*)(smem + ATTH_OFF);
    uint32_t* attl = (uint32_t*)(smem + ATTL_OFF);
    {
        const int row = tid >> 2, t4 = tid & 3;
        float* r0p = (float*)(smem + SCR0_OFF) + row * SCR_S;
        float* r1p = (float*)(smem + SCR1_OFF) + row * SCR_S;
        float vals[20];
        const int n0 = t4 * 20;
        const int n1 = (n0 + 20 < NW) ? n0 + 20 : NW;
        float mx = -1e30f;
        for (int n = n0; n < n1; n++) {
            float v = r0p[n] + r1p[n];
            vals[n - n0] = v;
            mx = fmaxf(mx, v);
        }
        mx = fmaxf(mx, __shfl_xor_sync(0xffffffffu, mx, 1));
        mx = fmaxf(mx, __shfl_xor_sync(0xffffffffu, mx, 2));
        float s = 0.f;
        for (int n = n0; n < n1; n++) {
            float e = __expf(vals[n - n0] - mx);
            vals[n - n0] = e;
            s += e;
        }
        s += __shfl_xor_sync(0xffffffffu, s, 1);
        s += __shfl_xor_sync(0xffffffffu, s, 2);
        const float inv = 1.f / s;
#pragma unroll
        for (int p = 0; p < 10; p++) {
            const int pp = t4 * 10 + p;
            float v0 = (2 * pp < n1 && 2 * pp >= n0)         ? vals[2 * pp - n0] * inv     : 0.f;
            float v1 = (2 * pp + 1 < n1 && 2 * pp + 1 >= n0) ? vals[2 * pp + 1 - n0] * inv : 0.f;
            uint32_t ph, pl;
            split2(v0, v1, ph, pl);
            atth[row * ATT_S + pp] = ph;
            attl[row * ATT_S + pp] = pl;
        }
    }
    __syncthreads();

    // ================= Phase 3: out = att @ weT (2rg x 4cg) =================
    const int rg3 = wid & 1;
    const int cg3 = wid >> 1;          // 0..3
    const int r03 = rg3 * 32;
    const int c0w3 = cg3 * 32;
    const uint32_t wlrow = (uint32_t)((lane >> 4) * 8 + ar) * SW3 +
                           (uint32_t)((lane >> 3) & 1) * 16;

    for (int oc = 0; oc < 8; oc++) {
        const int s = oc & 1;
        const uint32_t ws = s ? WS1_OFF : WS0_OFF;
        if (oc < 7) { load_W(oc + 1, (s ^ 1) ? WS1_OFF : WS0_OFF); CP_COMMIT(); }
        if (oc < 7) CP_WAIT1(); else CP_WAIT0();
        __syncthreads();

        float acc2[2][4][4];
#pragma unroll
        for (int mt = 0; mt < 2; mt++)
#pragma unroll
            for (int t = 0; t < 4; t++)
#pragma unroll
                for (int j = 0; j < 4; j++) acc2[mt][t][j] = 0.f;

#pragma unroll
        for (int ks = 0; ks < 5; ks++) {
            const int p0 = ks * 8 + q;
            uint32_t a_h[2][4], a_l[2][4];
#pragma unroll
            for (int mt = 0; mt < 2; mt++) {
                const int rr = r03 + mt * 16 + g;
                a_h[mt][0] = atth[rr * ATT_S + p0];
                a_h[mt][1] = atth[(rr + 8) * ATT_S + p0];
                a_h[mt][2] = atth[rr * ATT_S + p0 + 4];
                a_h[mt][3] = atth[(rr + 8) * ATT_S + p0 + 4];
                a_l[mt][0] = attl[rr * ATT_S + p0];
                a_l[mt][1] = attl[(rr + 8) * ATT_S + p0];
                a_l[mt][2] = attl[rr * ATT_S + p0 + 4];
                a_l[mt][3] = attl[(rr + 8) * ATT_S + p0 + 4];
            }
            const uint32_t kb = (uint32_t)ks * 32;
#pragma unroll
            for (int tp = 0; tp < 2; tp++) {
                uint32_t bo = (uint32_t)(c0w3 + tp * 16) * SW3 + wlrow + kb;
                uint32_t b_h[4], b_l[4];
                ldsm4(b_h, sb + ws + bo);
                ldsm4(b_l, sb + ws + W_HL + bo);
#pragma unroll
                for (int mt = 0; mt < 2; mt++) {
                    mma_bf16(acc2[mt][2 * tp],     a_h[mt], b_h[0], b_h[1]);
                    mma_bf16(acc2[mt][2 * tp],     a_h[mt], b_l[0], b_l[1]);
                    mma_bf16(acc2[mt][2 * tp],     a_l[mt], b_h[0], b_h[1]);
                    mma_bf16(acc2[mt][2 * tp + 1], a_h[mt], b_h[2], b_h[3]);
                    mma_bf16(acc2[mt][2 * tp + 1], a_h[mt], b_l[2], b_l[3]);
                    mma_bf16(acc2[mt][2 * tp + 1], a_l[mt], b_h[2], b_h[3]);
                }
            }
        }

        const int k0 = oc * 128;
#pragma unroll
        for (int mt = 0; mt < 2; mt++) {
            float* ob = out + ((size_t)b * CC + c0 + r03 + mt * 16) * HW2 + k0 + c0w3;
#pragma unroll
            for (int t = 0; t < 4; t++) {
                int col = t * 8 + 2 * q;
                *(float2*)&ob[(size_t)g * HW2 + col]       = make_float2(acc2[mt][t][0], acc2[mt][t][1]);
                *(float2*)&ob[(size_t)(g + 8) * HW2 + col] = make_float2(acc2[mt][t][2], acc2[mt][t][3]);
            }
        }
        __syncthreads();
    }
}

// ---------------------------------------------------------------------------
extern "C" void kernel_launch(void* const* d_in, const int* in_sizes, int n_in,
                              void* d_out, int out_size) {
    const float* feat     = (const float*)d_in[0];
    const float* word_emb = (const float*)d_in[1];
    const float* W_fc     = (const float*)d_in[2];
    const float* b_fc     = (const float*)d_in[3];
    float* out            = (float*)d_out;
    (void)in_sizes; (void)n_in; (void)out_size;

    cudaFuncSetAttribute(we_gemm_tc, cudaFuncAttributeMaxDynamicSharedMemorySize, G_SMEM);
    cudaFuncSetAttribute(attn_tc, cudaFuncAttributeMaxDynamicSharedMemorySize, SMEM_ATT);

    split_inputs<<<(A_TASKS + W_TASKS + 255) / 256, 256>>>(word_emb, W_fc);
    we_gemm_tc<<<dim3(HW2 / 128, MP / 64), 256, G_SMEM>>>(b_fc);    // (8, 40)
    transpose_we<<<dim3(HW2 / 64, BB), 256>>>();                    // (16, 32)
    attn_tc<<<dim3(CC / 64, BB), 256, SMEM_ATT>>>(feat, out);       // (8, 32)
}

// round 14
// speedup vs baseline: 3.1459x; 1.1068x over previous
#include <cuda_runtime.h>
#include <cuda_bf16.h>
#include <cstdint>

#define BB   32
#define CC   512
#define HW2  1024
#define NW   77
#define NP   80          // padded n
#define WD   256
#define MP   (BB * NP)   // 2560 padded rows

// ---------------- scratch ----------------
__device__ __nv_bfloat16 g_a_hi[(size_t)MP * WD];
__device__ __nv_bfloat16 g_a_lo[(size_t)MP * WD];
__device__ __nv_bfloat16 g_w_hi[(size_t)HW2 * WD];
__device__ __nv_bfloat16 g_w_lo[(size_t)HW2 * WD];
__device__ __nv_bfloat16 g_we_hi[(size_t)BB * NP * HW2];
__device__ __nv_bfloat16 g_we_lo[(size_t)BB * NP * HW2];

// ---------------- helpers ----------------
__device__ __forceinline__ uint32_t smem_to_u32(const void* p) {
    uint32_t a;
    asm("{ .reg .u64 t; cvta.to.shared.u64 t, %1; cvt.u32.u64 %0, t; }" : "=r"(a) : "l"(p));
    return a;
}
__device__ __forceinline__ void mma_bf16(float* c, const uint32_t* a, uint32_t b0, uint32_t b1) {
    asm volatile(
        "mma.sync.aligned.m16n8k16.row.col.f32.bf16.bf16.f32 "
        "{%0,%1,%2,%3}, {%4,%5,%6,%7}, {%8,%9}, {%0,%1,%2,%3};"
        : "+f"(c[0]), "+f"(c[1]), "+f"(c[2]), "+f"(c[3])
        : "r"(a[0]), "r"(a[1]), "r"(a[2]), "r"(a[3]), "r"(b0), "r"(b1));
}
__device__ __forceinline__ void ldsm4(uint32_t* r, uint32_t addr) {
    asm volatile("ldmatrix.sync.aligned.m8n8.x4.shared.b16 {%0,%1,%2,%3}, [%4];"
        : "=r"(r[0]), "=r"(r[1]), "=r"(r[2]), "=r"(r[3]) : "r"(addr));
}
__device__ __forceinline__ void ldsm4t(uint32_t* r, uint32_t addr) {
    asm volatile("ldmatrix.sync.aligned.m8n8.x4.trans.shared.b16 {%0,%1,%2,%3}, [%4];"
        : "=r"(r[0]), "=r"(r[1]), "=r"(r[2]), "=r"(r[3]) : "r"(addr));
}
__device__ __forceinline__ void split2(float v0, float v1, uint32_t& ph, uint32_t& pl) {
    __nv_bfloat16 h0 = __float2bfloat16(v0), h1 = __float2bfloat16(v1);
    float r0 = v0 - __bfloat162float(h0), r1 = v1 - __bfloat162float(h1);
    __nv_bfloat16 l0 = __float2bfloat16(r0), l1 = __float2bfloat16(r1);
    ph = (uint32_t)__bfloat16_as_ushort(h0) | ((uint32_t)__bfloat16_as_ushort(h1) << 16);
    pl = (uint32_t)__bfloat16_as_ushort(l0) | ((uint32_t)__bfloat16_as_ushort(l1) << 16);
}
#define CP16(dst, src) asm volatile("cp.async.cg.shared.global [%0], [%1], 16;" :: "r"(dst), "l"(src))
#define CP_COMMIT()    asm volatile("cp.async.commit_group;" ::: "memory")
#define CP_WAIT0()     asm volatile("cp.async.wait_group 0;" ::: "memory")
#define CP_WAIT1()     asm volatile("cp.async.wait_group 1;" ::: "memory")

#define SA  144

// ---------------------------------------------------------------------------
// Kernel 0: elementwise bf16 hi/lo split of word_emb (padded) + W_fc
// ---------------------------------------------------------------------------
#define A_TASKS (MP * WD / 4)
#define W_TASKS (HW2 * WD / 4)
__global__ void split_inputs(const float* __restrict__ we_in,
                             const float* __restrict__ Wfc) {
    int idx = blockIdx.x * 256 + threadIdx.x;
    if (idx < A_TASKS) {
        int mp = idx >> 6, c4 = idx & 63;
        int bb = mp / NP, nn = mp % NP;
        float4 v = make_float4(0.f, 0.f, 0.f, 0.f);
        if (nn < NW) v = *(const float4*)(we_in + ((size_t)bb * NW + nn) * WD + c4 * 4);
        uint32_t h0, l0, h1, l1;
        split2(v.x, v.y, h0, l0);
        split2(v.z, v.w, h1, l1);
        *(uint2*)(g_a_hi + (size_t)mp * WD + c4 * 4) = make_uint2(h0, h1);
        *(uint2*)(g_a_lo + (size_t)mp * WD + c4 * 4) = make_uint2(l0, l1);
    } else if (idx < A_TASKS + W_TASKS) {
        int j = idx - A_TASKS;
        int r = j >> 6, c4 = j & 63;
        float4 v = *(const float4*)(Wfc + (size_t)r * WD + c4 * 4);
        uint32_t h0, l0, h1, l1;
        split2(v.x, v.y, h0, l0);
        split2(v.z, v.w, h1, l1);
        *(uint2*)(g_w_hi + (size_t)r * WD + c4 * 4) = make_uint2(h0, h1);
        *(uint2*)(g_w_lo + (size_t)r * WD + c4 * 4) = make_uint2(l0, l1);
    }
}

// ---------------------------------------------------------------------------
// Kernel 1: we = word_emb @ W_fc^T + b_fc (bf16 GEMM, cp.async 2-stage)
// (unchanged — 64-row CTAs, 8 warps = 4rg x 2cg)
// ---------------------------------------------------------------------------
#define G_AH 0
#define G_AL 9216
#define G_BH 18432
#define G_BL 36864
#define G_STAGE 55296
#define G_SMEM  110592

__global__ __launch_bounds__(256, 2) void we_gemm_tc(const float* __restrict__ bfc) {
    extern __shared__ char smem[];
    const uint32_t sb = smem_to_u32(smem);
    const int tid  = threadIdx.x;
    const int wid  = tid >> 5;
    const int lane = tid & 31;
    const int q    = lane & 3;
    const int g    = lane >> 2;
    const int rg   = wid & 3;
    const int cg   = wid >> 2;
    const int m0   = blockIdx.y * 64;
    const int k0   = blockIdx.x * 128;
    const int r0   = rg * 16;
    const int c0w  = cg * 64;

    float acc[8][4];
#pragma unroll
    for (int t = 0; t < 8; t++)
#pragma unroll
        for (int j = 0; j < 4; j++) acc[t][j] = 0.f;

    const int am = lane >> 3;
    const int ar = lane & 7;
    const uint32_t arow = (uint32_t)((am & 1) * 8 + ar) * SA + (uint32_t)(am >> 1) * 16;
    const uint32_t b4row = (uint32_t)((lane >> 4) * 8 + ar) * SA + (uint32_t)((lane >> 3) & 1) * 16;

    auto load_chunk = [&](int ch, int s) {
        const int kc = ch * 64;
        const uint32_t st = sb + (uint32_t)s * G_STAGE;
        for (int i = tid; i < 1024; i += 256) {
            int r = i >> 3, c = i & 7;
            uint32_t off = (uint32_t)r * SA + (uint32_t)c * 16;
            CP16(st + G_BH + off, g_w_hi + (size_t)(k0 + r) * WD + kc + c * 8);
            CP16(st + G_BL + off, g_w_lo + (size_t)(k0 + r) * WD + kc + c * 8);
            if (r < 64) {
                CP16(st + G_AH + off, g_a_hi + (size_t)(m0 + r) * WD + kc + c * 8);
                CP16(st + G_AL + off, g_a_lo + (size_t)(m0 + r) * WD + kc + c * 8);
            }
        }
    };

    load_chunk(0, 0);
    CP_COMMIT();

    for (int ch = 0; ch < 4; ch++) {
        const int s = ch & 1;
        if (ch < 3) { load_chunk(ch + 1, s ^ 1); CP_COMMIT(); }
        if (ch < 3) CP_WAIT1(); else CP_WAIT0();
        __syncthreads();

        const uint32_t st = sb + (uint32_t)s * G_STAGE;
#pragma unroll
        for (int ks = 0; ks < 4; ks++) {
            const uint32_t kb = (uint32_t)ks * 32;
            uint32_t a_h[4], a_l[4];
            {
                uint32_t ao = (uint32_t)r0 * SA + arow + kb;
                ldsm4(a_h, st + G_AH + ao);
                ldsm4(a_l, st + G_AL + ao);
            }
#pragma unroll
            for (int tp = 0; tp < 4; tp++) {
                uint32_t bo = (uint32_t)(c0w + tp * 16) * SA + b4row + kb;
                uint32_t b_h[4], b_l[4];
                ldsm4(b_h, st + G_BH + bo);
                ldsm4(b_l, st + G_BL + bo);
                mma_bf16(acc[2 * tp],     a_h, b_h[0], b_h[1]);
                mma_bf16(acc[2 * tp],     a_h, b_l[0], b_l[1]);
                mma_bf16(acc[2 * tp],     a_l, b_h[0], b_h[1]);
                mma_bf16(acc[2 * tp + 1], a_h, b_h[2], b_h[3]);
                mma_bf16(acc[2 * tp + 1], a_h, b_l[2], b_l[3]);
                mma_bf16(acc[2 * tp + 1], a_l, b_h[2], b_h[3]);
            }
        }
        __syncthreads();
    }

    const int mp0 = m0 + r0 + g;
    const int mp1 = mp0 + 8;
    const bool v0ok = ((mp0 % NP) < NW);
    const bool v1ok = ((mp1 % NP) < NW);
#pragma unroll
    for (int t = 0; t < 8; t++) {
        const int col = k0 + c0w + t * 8 + 2 * q;
        const float b0 = bfc[col], b1 = bfc[col + 1];
        float v00 = v0ok ? acc[t][0] + b0 : 0.f;
        float v01 = v0ok ? acc[t][1] + b1 : 0.f;
        float v10 = v1ok ? acc[t][2] + b0 : 0.f;
        float v11 = v1ok ? acc[t][3] + b1 : 0.f;
        uint32_t ph, pl;
        split2(v00, v01, ph, pl);
        *(uint32_t*)(g_we_hi + (size_t)mp0 * HW2 + col) = ph;
        *(uint32_t*)(g_we_lo + (size_t)mp0 * HW2 + col) = pl;
        split2(v10, v11, ph, pl);
        *(uint32_t*)(g_we_hi + (size_t)mp1 * HW2 + col) = ph;
        *(uint32_t*)(g_we_lo + (size_t)mp1 * HW2 + col) = pl;
    }
}

// ---------------------------------------------------------------------------
// Kernel 2: fused attention, 64-row CTAs, 256 threads.
// Phase 1: 8 warps = 2rg x 2cg x 2kh (unchanged).
// Phase 3: B-frags from we (n-major) via ldmatrix.trans — no transpose kernel;
//          att A-frags via ldsm4 (pitch 44 words, conflict-free).
// ---------------------------------------------------------------------------
#define P1_AH 0
#define P1_AL 9216
#define P1_BH 18432
#define P1_BL 29952
#define P1_STAGE 41472
// overlays
#define SCR0_OFF 0          // fp32 [64][81]
#define SCR1_OFF 20736
#define SCR_S    81
#define WS_A     43520      // W stage A (prefetched during softmax; clear of SCR)
#define WS_B     0          // W stage B (used after softmax)
#define W_PITCH  272        // 80 n-rows x (128k + 8 pad) bf16
#define W_HL     21760      // lo offset within a W stage (80*272)
#define ATTH_OFF 87040      // uint32 [64][44]
#define ATTL_OFF 98304
#define ATT_S    44
#define SMEM_ATT 109568

__global__ __launch_bounds__(256, 2) void attn_tc(const float* __restrict__ feat,
                                                  float* __restrict__ out) {
    extern __shared__ char smem[];
    const uint32_t sb = smem_to_u32(smem);
    const int tid  = threadIdx.x;
    const int wid  = tid >> 5;
    const int lane = tid & 31;
    const int q    = lane & 3;
    const int g    = lane >> 2;
    const int b    = blockIdx.y;
    const int c0   = blockIdx.x * 64;

    // phase-1 warp roles
    const int rg1 = wid & 1;
    const int cg1 = (wid >> 1) & 1;
    const int kh1 = wid >> 2;
    const int r01 = rg1 * 32;
    const int c0w = cg1 * 40;

    const float* fb = feat + ((size_t)b * CC + c0) * HW2;
    const __nv_bfloat16* weh = g_we_hi + (size_t)b * NP * HW2;
    const __nv_bfloat16* wel = g_we_lo + (size_t)b * NP * HW2;

    const int ar = lane & 7;
    const int lb3 = (lane >> 3) & 1;
    const int lb4 = lane >> 4;
    const int am = lane >> 3;
    const uint32_t arow = (uint32_t)((am & 1) * 8 + ar) * SA + (uint32_t)(am >> 1) * 16;
    const uint32_t b4row = (uint32_t)(lb4 * 8 + ar) * SA + (uint32_t)lb3 * 16;
    const uint32_t cmb_base = (uint32_t)((lane < 16) ? P1_BH : P1_BL) +
                              (uint32_t)(c0w + 32 + ar) * SA +
                              (uint32_t)lb3 * 16;

    // ---- phase-1 loaders ----
    const int lr = tid >> 2, lh = tid & 3;
    auto load_A_regs = [&](int ch, float4* pf) {
        const float* src = fb + (size_t)lr * HW2 + ch * 64 + lh * 16;
#pragma unroll
        for (int i = 0; i < 4; i++) pf[i] = *(const float4*)(src + i * 4);
    };
    auto store_A = [&](int s, const float4* pf) {
        uint32_t h[8], l[8];
#pragma unroll
        for (int i = 0; i < 4; i++) {
            split2(pf[i].x, pf[i].y, h[2 * i], l[2 * i]);
            split2(pf[i].z, pf[i].w, h[2 * i + 1], l[2 * i + 1]);
        }
        uint4* ph_ = (uint4*)(smem + s * P1_STAGE + P1_AH + lr * SA + lh * 32);
        uint4* pl_ = (uint4*)(smem + s * P1_STAGE + P1_AL + lr * SA + lh * 32);
        ph_[0] = make_uint4(h[0], h[1], h[2], h[3]);
        ph_[1] = make_uint4(h[4], h[5], h[6], h[7]);
        pl_[0] = make_uint4(l[0], l[1], l[2], l[3]);
        pl_[1] = make_uint4(l[4], l[5], l[6], l[7]);
    };
    auto load_B = [&](int ch, int s) {
        const int kc = ch * 64;
        const uint32_t st = sb + (uint32_t)s * P1_STAGE;
        for (int i = tid; i < 640; i += 256) {
            int r = i >> 3, cch = i & 7;
            uint32_t off = (uint32_t)r * SA + (uint32_t)cch * 16;
            CP16(st + P1_BH + off, weh + (size_t)r * HW2 + kc + cch * 8);
            CP16(st + P1_BL + off, wel + (size_t)r * HW2 + kc + cch * 8);
        }
    };

    // ================= Phase 1: partial scores (K-split) =================
    float acc[2][5][4];
#pragma unroll
    for (int mt = 0; mt < 2; mt++)
#pragma unroll
        for (int t = 0; t < 5; t++)
#pragma unroll
            for (int j = 0; j < 4; j++) acc[mt][t][j] = 0.f;

    float4 pf[4];
    load_A_regs(0, pf);
    load_B(0, 0);
    CP_COMMIT();
    store_A(0, pf);

    for (int it = 0; it < 16; it++) {
        const int s = it & 1;
        if (it < 15) {
            load_A_regs(it + 1, pf);
            load_B(it + 1, s ^ 1);
            CP_COMMIT();
        }
        if (it < 15) CP_WAIT1(); else CP_WAIT0();
        __syncthreads();

        const uint32_t st = sb + (uint32_t)s * P1_STAGE;
#pragma unroll
        for (int ks = 0; ks < 2; ks++) {
            const uint32_t kb = (uint32_t)(kh1 * 64 + ks * 32);
            uint32_t a_h[2][4], a_l[2][4];
#pragma unroll
            for (int mt = 0; mt < 2; mt++) {
                uint32_t ao = (uint32_t)(r01 + mt * 16) * SA + arow + kb;
                ldsm4(a_h[mt], st + P1_AH + ao);
                ldsm4(a_l[mt], st + P1_AL + ao);
            }
            uint32_t b_h[2][4], b_l[2][4], bc[4];
#pragma unroll
            for (int tp = 0; tp < 2; tp++) {
                uint32_t bo = (uint32_t)(c0w + tp * 16) * SA + b4row + kb;
                ldsm4(b_h[tp], st + P1_BH + bo);
                ldsm4(b_l[tp], st + P1_BL + bo);
            }
            ldsm4(bc, st + cmb_base + kb);
#pragma unroll
            for (int mt = 0; mt < 2; mt++) {
#pragma unroll
                for (int tp = 0; tp < 2; tp++) {
                    mma_bf16(acc[mt][2 * tp],     a_h[mt], b_h[tp][0], b_h[tp][1]);
                    mma_bf16(acc[mt][2 * tp],     a_h[mt], b_l[tp][0], b_l[tp][1]);
                    mma_bf16(acc[mt][2 * tp],     a_l[mt], b_h[tp][0], b_h[tp][1]);
                    mma_bf16(acc[mt][2 * tp + 1], a_h[mt], b_h[tp][2], b_h[tp][3]);
                    mma_bf16(acc[mt][2 * tp + 1], a_h[mt], b_l[tp][2], b_l[tp][3]);
                    mma_bf16(acc[mt][2 * tp + 1], a_l[mt], b_h[tp][2], b_h[tp][3]);
                }
                mma_bf16(acc[mt][4], a_h[mt], bc[0], bc[1]);
                mma_bf16(acc[mt][4], a_h[mt], bc[2], bc[3]);
                mma_bf16(acc[mt][4], a_l[mt], bc[0], bc[1]);
            }
        }
        if (it < 15) store_A(s ^ 1, pf);
        __syncthreads();
    }

    // ---- write partial scores ----
    float* myscr = (float*)(smem + (kh1 ? SCR1_OFF : SCR0_OFF));
#pragma unroll
    for (int mt = 0; mt < 2; mt++) {
        const int row0 = r01 + mt * 16 + g;
#pragma unroll
        for (int t = 0; t < 5; t++) {
            const int col = c0w + t * 8 + 2 * q;
            myscr[row0 * SCR_S + col]       = acc[mt][t][0];
            myscr[row0 * SCR_S + col + 1]   = acc[mt][t][1];
            myscr[(row0 + 8) * SCR_S + col]     = acc[mt][t][2];
            myscr[(row0 + 8) * SCR_S + col + 1] = acc[mt][t][3];
        }
    }
    __syncthreads();

    // ================= Phase 2: prefetch W0 + softmax =================
    auto load_W = [&](int oc, uint32_t ws) {
        const int k0 = oc * 128;
        for (int i = tid; i < 1280; i += 256) {
            int r = i >> 4, c = i & 15;
            uint32_t off = (uint32_t)r * W_PITCH + (uint32_t)c * 16;
            CP16(sb + ws + off, weh + (size_t)r * HW2 + k0 + c * 8);
            CP16(sb + ws + W_HL + off, wel + (size_t)r * HW2 + k0 + c * 8);
        }
    };
    load_W(0, WS_A);
    CP_COMMIT();

    uint32_t* atth = (uint32_t*)(smem + ATTH_OFF);
    uint32_t* attl = (uint32_t*)(smem + ATTL_OFF);
    {
        const int row = tid >> 2, t4 = tid & 3;
        float* r0p = (float*)(smem + SCR0_OFF) + row * SCR_S;
        float* r1p = (float*)(smem + SCR1_OFF) + row * SCR_S;
        float vals[20];
        const int n0 = t4 * 20;
        const int n1 = (n0 + 20 < NW) ? n0 + 20 : NW;
        float mx = -1e30f;
        for (int n = n0; n < n1; n++) {
            float v = r0p[n] + r1p[n];
            vals[n - n0] = v;
            mx = fmaxf(mx, v);
        }
        mx = fmaxf(mx, __shfl_xor_sync(0xffffffffu, mx, 1));
        mx = fmaxf(mx, __shfl_xor_sync(0xffffffffu, mx, 2));
        float s = 0.f;
        for (int n = n0; n < n1; n++) {
            float e = __expf(vals[n - n0] - mx);
            vals[n - n0] = e;
            s += e;
        }
        s += __shfl_xor_sync(0xffffffffu, s, 1);
        s += __shfl_xor_sync(0xffffffffu, s, 2);
        const float inv = 1.f / s;
#pragma unroll
        for (int p = 0; p < 10; p++) {
            const int pp = t4 * 10 + p;
            float v0 = (2 * pp < n1 && 2 * pp >= n0)         ? vals[2 * pp - n0] * inv     : 0.f;
            float v1 = (2 * pp + 1 < n1 && 2 * pp + 1 >= n0) ? vals[2 * pp + 1 - n0] * inv : 0.f;
            uint32_t ph, pl;
            split2(v0, v1, ph, pl);
            atth[row * ATT_S + pp] = ph;
            attl[row * ATT_S + pp] = pl;
        }
    }
    __syncthreads();

    // ================= Phase 3: out = att @ we (ldsm.trans B) =================
    const int rg3 = wid & 1;
    const int cg3 = wid >> 1;          // 0..3 -> 32 k-cols each
    const int r03 = rg3 * 32;
    const int c0w3 = cg3 * 32;

    for (int oc = 0; oc < 8; oc++) {
        const uint32_t ws = (oc & 1) ? WS_B : WS_A;
        if (oc < 7) { load_W(oc + 1, (oc & 1) ? WS_A : WS_B); CP_COMMIT(); }
        if (oc < 7) CP_WAIT1(); else CP_WAIT0();
        __syncthreads();

        float acc2[2][4][4];
#pragma unroll
        for (int mt = 0; mt < 2; mt++)
#pragma unroll
            for (int t = 0; t < 4; t++)
#pragma unroll
                for (int j = 0; j < 4; j++) acc2[mt][t][j] = 0.f;

#pragma unroll
        for (int ks = 0; ks < 5; ks++) {
            // att A-frags via ldsm4 (non-trans)
            uint32_t a_h[2][4], a_l[2][4];
#pragma unroll
            for (int mt = 0; mt < 2; mt++) {
                uint32_t aoff = ((uint32_t)(r03 + mt * 16 + ar + lb3 * 8) * ATT_S +
                                 (uint32_t)(ks * 8 + lb4 * 4)) * 4;
                ldsm4(a_h[mt], sb + ATTH_OFF + aoff);
                ldsm4(a_l[mt], sb + ATTL_OFF + aoff);
            }
            // we B-frags via ldsm4.trans: source rows = n, cols = k
#pragma unroll
            for (int tp = 0; tp < 2; tp++) {
                uint32_t woff = (uint32_t)(ks * 16 + ar + lb3 * 8) * W_PITCH +
                                (uint32_t)(c0w3 + tp * 16 + lb4 * 8) * 2;
                uint32_t b_h[4], b_l[4];
                ldsm4t(b_h, sb + ws + woff);
                ldsm4t(b_l, sb + ws + W_HL + woff);
#pragma unroll
                for (int mt = 0; mt < 2; mt++) {
                    mma_bf16(acc2[mt][2 * tp],     a_h[mt], b_h[0], b_h[1]);
                    mma_bf16(acc2[mt][2 * tp],     a_h[mt], b_l[0], b_l[1]);
                    mma_bf16(acc2[mt][2 * tp],     a_l[mt], b_h[0], b_h[1]);
                    mma_bf16(acc2[mt][2 * tp + 1], a_h[mt], b_h[2], b_h[3]);
                    mma_bf16(acc2[mt][2 * tp + 1], a_h[mt], b_l[2], b_l[3]);
                    mma_bf16(acc2[mt][2 * tp + 1], a_l[mt], b_h[2], b_h[3]);
                }
            }
        }

        const int k0 = oc * 128;
#pragma unroll
        for (int mt = 0; mt < 2; mt++) {
            float* ob = out + ((size_t)b * CC + c0 + r03 + mt * 16) * HW2 + k0 + c0w3;
#pragma unroll
            for (int t = 0; t < 4; t++) {
                int col = t * 8 + 2 * q;
                *(float2*)&ob[(size_t)g * HW2 + col]       = make_float2(acc2[mt][t][0], acc2[mt][t][1]);
                *(float2*)&ob[(size_t)(g + 8) * HW2 + col] = make_float2(acc2[mt][t][2], acc2[mt][t][3]);
            }
        }
        __syncthreads();
    }
}

// ---------------------------------------------------------------------------
extern "C" void kernel_launch(void* const* d_in, const int* in_sizes, int n_in,
                              void* d_out, int out_size) {
    const float* feat     = (const float*)d_in[0];
    const float* word_emb = (const float*)d_in[1];
    const float* W_fc     = (const float*)d_in[2];
    const float* b_fc     = (const float*)d_in[3];
    float* out            = (float*)d_out;
    (void)in_sizes; (void)n_in; (void)out_size;

    cudaFuncSetAttribute(we_gemm_tc, cudaFuncAttributeMaxDynamicSharedMemorySize, G_SMEM);
    cudaFuncSetAttribute(attn_tc, cudaFuncAttributeMaxDynamicSharedMemorySize, SMEM_ATT);

    split_inputs<<<(A_TASKS + W_TASKS + 255) / 256, 256>>>(word_emb, W_fc);
    we_gemm_tc<<<dim3(HW2 / 128, MP / 64), 256, G_SMEM>>>(b_fc);    // (8, 40)
    attn_tc<<<dim3(CC / 64, BB), 256, SMEM_ATT>>>(feat, out);       // (8, 32)
}